// round 1
// baseline (speedup 1.0000x reference)
#include <cuda_runtime.h>

#define B_      8
#define C_      512
#define T_      1024
#define HEADS_  8
#define CH_     64
#define S_      77
#define L_      1101
#define GROUPS_ 32
#define CPG_    16
#define PAD     68

// Scratch (static device globals; no dynamic allocation allowed)
static __device__ float g_nrm[B_ * C_ * T_];          // 16.8 MB
static __device__ float g_qkv[B_ * 3 * C_ * T_];      // 50.3 MB
static __device__ float g_ekv[B_ * 2 * C_ * S_];      //  2.5 MB
static __device__ float g_att[B_ * C_ * T_];          // 16.8 MB

// ---------------------------------------------------------------------------
// GroupNorm32: one block per (batch, group). 16 channels x 1024 = 16384 elems.
// ---------------------------------------------------------------------------
__global__ __launch_bounds__(256) void gn_kernel(
    const float* __restrict__ x, const float* __restrict__ gamma,
    const float* __restrict__ beta, float* __restrict__ out)
{
    int b = blockIdx.x / GROUPS_, g = blockIdx.x % GROUPS_;
    const float* xp = x + ((size_t)b * C_ + g * CPG_) * T_;
    float* op = out + ((size_t)b * C_ + g * CPG_) * T_;
    const int N = CPG_ * T_;

    float s = 0.f, q = 0.f;
    for (int i = threadIdx.x; i < N; i += 256) {
        float v = xp[i];
        s += v;
        q = fmaf(v, v, q);
    }
    __shared__ float rs[256], rq[256];
    rs[threadIdx.x] = s; rq[threadIdx.x] = q;
    __syncthreads();
    for (int o = 128; o > 0; o >>= 1) {
        if (threadIdx.x < o) {
            rs[threadIdx.x] += rs[threadIdx.x + o];
            rq[threadIdx.x] += rq[threadIdx.x + o];
        }
        __syncthreads();
    }
    float mean = rs[0] * (1.f / N);
    float var  = rq[0] * (1.f / N) - mean * mean;
    float inv  = rsqrtf(var + 1e-5f);
    for (int i = threadIdx.x; i < N; i += 256) {
        int c = g * CPG_ + (i >> 10);
        op[i] = (xp[i] - mean) * inv * gamma[c] + beta[c];
    }
}

// ---------------------------------------------------------------------------
// Generic fp32 GEMM:  C[z][m][n] = sum_k A[m][k] * B[z][k][n] + bias[m] (+res)
// Tile 128x128, K-step 16, 256 threads, 8x8 micro-tile. M%128==0, K%16==0.
// ---------------------------------------------------------------------------
__global__ __launch_bounds__(256) void gemm_kernel(
    const float* __restrict__ A, const float* __restrict__ Bm,
    const float* __restrict__ bias, const float* __restrict__ res,
    float* __restrict__ Cm, int M, int N, int K,
    int ldb, long long sB, int ldc, long long sC)
{
    __shared__ float As[16][132];   // [k][m], padded
    __shared__ float Bs[16][128];   // [k][n]

    const float* Bp = Bm + (size_t)blockIdx.z * sB;
    float* Cp = Cm + (size_t)blockIdx.z * sC;
    const float* Rp = res ? (res + (size_t)blockIdx.z * sC) : nullptr;

    int bm = blockIdx.y << 7, bn = blockIdx.x << 7;
    int tid = threadIdx.x, tx = tid & 15, ty = tid >> 4;

    float acc[8][8];
#pragma unroll
    for (int i = 0; i < 8; i++)
#pragma unroll
        for (int j = 0; j < 8; j++) acc[i][j] = 0.f;

    for (int k0 = 0; k0 < K; k0 += 16) {
#pragma unroll
        for (int l = 0; l < 8; l++) {
            int idx = tid + (l << 8);
            As[idx & 15][idx >> 4] = A[(size_t)(bm + (idx >> 4)) * K + k0 + (idx & 15)];
        }
#pragma unroll
        for (int l = 0; l < 8; l++) {
            int idx = tid + (l << 8);
            int n = idx & 127, k = idx >> 7;
            int gn = bn + n;
            Bs[k][n] = (gn < N) ? Bp[(size_t)(k0 + k) * ldb + gn] : 0.f;
        }
        __syncthreads();
#pragma unroll
        for (int k = 0; k < 16; k++) {
            float4 a0 = *(const float4*)&As[k][ty * 8];
            float4 a1 = *(const float4*)&As[k][ty * 8 + 4];
            float4 b0 = *(const float4*)&Bs[k][tx * 8];
            float4 b1 = *(const float4*)&Bs[k][tx * 8 + 4];
            float ra[8] = {a0.x, a0.y, a0.z, a0.w, a1.x, a1.y, a1.z, a1.w};
            float rb[8] = {b0.x, b0.y, b0.z, b0.w, b1.x, b1.y, b1.z, b1.w};
#pragma unroll
            for (int i = 0; i < 8; i++)
#pragma unroll
                for (int j = 0; j < 8; j++)
                    acc[i][j] = fmaf(ra[i], rb[j], acc[i][j]);
        }
        __syncthreads();
    }

#pragma unroll
    for (int i = 0; i < 8; i++) {
        int m = bm + ty * 8 + i;
        float bv = bias[m];
#pragma unroll
        for (int j = 0; j < 8; j++) {
            int n = bn + tx * 8 + j;
            if (n < N) {
                float v = acc[i][j] + bv;
                if (Rp) v += Rp[(size_t)m * ldc + n];
                Cp[(size_t)m * ldc + n] = v;
            }
        }
    }
}

// ---------------------------------------------------------------------------
// Flash attention: block per (bh, 64-query tile). CH=64, chunks of 64 keys.
// smem: qs[ch][t], ks[ch][s], vsT[s][ch], psT[s][t]  (all [64][PAD])
// ---------------------------------------------------------------------------
__global__ __launch_bounds__(256) void attn_kernel(const unsigned int* __restrict__ mask)
{
    extern __shared__ float sm[];
    float (*qs)[PAD]  = (float(*)[PAD])sm;
    float (*ks)[PAD]  = qs + 64;
    float (*vsT)[PAD] = ks + 64;
    float (*psT)[PAD] = vsT + 64;
    float* mrow    = (float*)(psT + 64);
    float* lrow    = mrow + 64;
    float* srow    = lrow + 64;
    float* maskadd = srow + 64;   // 80 slots, first 77 used

    int bh = blockIdx.y;
    int b = bh >> 3, h = bh & 7;
    int t0 = blockIdx.x << 6;
    int tid = threadIdx.x;
    int tx = tid & 15, ty = tid >> 4;

    const float* qb  = g_qkv + ((size_t)b * 3 * C_ + h * 192) * T_ + t0;
    const float* kb  = g_qkv + ((size_t)b * 3 * C_ + h * 192 + 64) * T_;
    const float* vb  = g_qkv + ((size_t)b * 3 * C_ + h * 192 + 128) * T_;
    const float* keb = g_ekv + ((size_t)b * 2 * C_ + h * 128) * S_;
    const float* veb = g_ekv + ((size_t)b * 2 * C_ + h * 128 + 64) * S_;

    int mr = bh % B_;   // torch.tile head-major quirk
    for (int s = tid; s < S_; s += 256)
        maskadd[s] = mask[mr * S_ + s] ? 0.f : -10000.f;

#pragma unroll
    for (int l = 0; l < 16; l++) {
        int idx = tid + (l << 8);
        int ch = idx >> 6, t = idx & 63;
        qs[ch][t] = qb[(size_t)ch * T_ + t] * 0.125f;   // scale^2 = 1/8 (exact)
    }
    if (tid < 64) { mrow[tid] = -1e30f; lrow[tid] = 0.f; }
    __syncthreads();

    float out[4][4];
#pragma unroll
    for (int i = 0; i < 4; i++)
#pragma unroll
        for (int j = 0; j < 4; j++) out[i][j] = 0.f;

    for (int c0 = 0; c0 < L_; c0 += 64) {
        // load K chunk [ch][s] and V chunk transposed [s][ch]
#pragma unroll
        for (int l = 0; l < 16; l++) {
            int idx = tid + (l << 8);
            int ch = idx >> 6, sl = idx & 63, s = c0 + sl;
            float kv = 0.f, vv = 0.f;
            if (s < S_)      { kv = keb[ch * S_ + s]; vv = veb[ch * S_ + s]; }
            else if (s < L_) { int t = s - S_; kv = kb[(size_t)ch * T_ + t]; vv = vb[(size_t)ch * T_ + t]; }
            ks[ch][sl] = kv;
            vsT[sl][ch] = vv;
        }
        __syncthreads();

        // scores: sc[t][s] = sum_ch q[ch][t] * k[ch][s]
        float sc[4][4];
#pragma unroll
        for (int i = 0; i < 4; i++)
#pragma unroll
            for (int j = 0; j < 4; j++) sc[i][j] = 0.f;
#pragma unroll
        for (int ch = 0; ch < 64; ch++) {
            float4 a = *(const float4*)&qs[ch][ty << 2];
            float4 k4 = *(const float4*)&ks[ch][tx << 2];
            float ra[4] = {a.x, a.y, a.z, a.w};
            float rb[4] = {k4.x, k4.y, k4.z, k4.w};
#pragma unroll
            for (int i = 0; i < 4; i++)
#pragma unroll
                for (int j = 0; j < 4; j++)
                    sc[i][j] = fmaf(ra[i], rb[j], sc[i][j]);
        }
        // mask + bounds, write transposed psT[s][t] (float4 along t)
#pragma unroll
        for (int j = 0; j < 4; j++) {
            int s = c0 + (tx << 2) + j;
            float add = (s < S_) ? maskadd[s] : 0.f;
            bool oob = (s >= L_);
            float4 w;
            w.x = oob ? -1e30f : sc[0][j] + add;
            w.y = oob ? -1e30f : sc[1][j] + add;
            w.z = oob ? -1e30f : sc[2][j] + add;
            w.w = oob ? -1e30f : sc[3][j] + add;
            *(float4*)&psT[(tx << 2) + j][ty << 2] = w;
        }
        __syncthreads();

        // online-softmax row stats: row r handled by 4 lanes (tid&3)
        {
            int r = tid >> 2, lane = tid & 3;
            float mx = -1e30f;
#pragma unroll
            for (int k = 0; k < 16; k++) mx = fmaxf(mx, psT[lane + (k << 2)][r]);
            mx = fmaxf(mx, __shfl_xor_sync(0xffffffffu, mx, 1));
            mx = fmaxf(mx, __shfl_xor_sync(0xffffffffu, mx, 2));
            float newm = fmaxf(mrow[r], mx);
            float es = 0.f;
#pragma unroll
            for (int k = 0; k < 16; k++) {
                int s = lane + (k << 2);
                float p = __expf(psT[s][r] - newm);
                psT[s][r] = p;
                es += p;
            }
            es += __shfl_xor_sync(0xffffffffu, es, 1);
            es += __shfl_xor_sync(0xffffffffu, es, 2);
            if (lane == 0) {
                float f = __expf(mrow[r] - newm);
                srow[r] = f;
                lrow[r] = lrow[r] * f + es;
                mrow[r] = newm;
            }
        }
        __syncthreads();

        // out[t][ch] = out*rescale + P @ V^T  (both operands float4 from smem)
        float rs4[4];
#pragma unroll
        for (int i = 0; i < 4; i++) rs4[i] = srow[(ty << 2) + i];
#pragma unroll
        for (int i = 0; i < 4; i++)
#pragma unroll
            for (int j = 0; j < 4; j++) out[i][j] *= rs4[i];
#pragma unroll
        for (int s = 0; s < 64; s++) {
            float4 p4 = *(const float4*)&psT[s][ty << 2];
            float4 v4 = *(const float4*)&vsT[s][tx << 2];
            float rp[4] = {p4.x, p4.y, p4.z, p4.w};
            float rv[4] = {v4.x, v4.y, v4.z, v4.w};
#pragma unroll
            for (int i = 0; i < 4; i++)
#pragma unroll
                for (int j = 0; j < 4; j++)
                    out[i][j] = fmaf(rp[i], rv[j], out[i][j]);
        }
        __syncthreads();
    }

    // epilogue: divide by l, transpose through smem for coalesced [ch][t] write
    float inv[4];
#pragma unroll
    for (int i = 0; i < 4; i++) inv[i] = 1.f / lrow[(ty << 2) + i];
#pragma unroll
    for (int i = 0; i < 4; i++)
#pragma unroll
        for (int j = 0; j < 4; j++)
            qs[(tx << 2) + j][(ty << 2) + i] = out[i][j] * inv[i];
    __syncthreads();

    float* ob = g_att + ((size_t)b * C_ + h * CH_) * T_ + t0;
#pragma unroll
    for (int l = 0; l < 16; l++) {
        int idx = tid + (l << 8);
        int ch = idx >> 6, t = idx & 63;
        ob[(size_t)ch * T_ + t] = qs[ch][t];
    }
}

// ---------------------------------------------------------------------------
extern "C" void kernel_launch(void* const* d_in, const int* in_sizes, int n_in,
                              void* d_out, int out_size)
{
    (void)in_sizes; (void)n_in; (void)out_size;
    const float* x       = (const float*)d_in[0];
    const float* enc     = (const float*)d_in[1];
    const unsigned int* mask = (const unsigned int*)d_in[2];
    const float* gamma   = (const float*)d_in[3];
    const float* beta    = (const float*)d_in[4];
    const float* qkv_w   = (const float*)d_in[5];
    const float* qkv_b   = (const float*)d_in[6];
    const float* ekv_w   = (const float*)d_in[7];
    const float* ekv_b   = (const float*)d_in[8];
    const float* proj_w  = (const float*)d_in[9];
    const float* proj_b  = (const float*)d_in[10];
    float* out = (float*)d_out;

    float *nrm, *qkv, *ekv, *att;
    cudaGetSymbolAddress((void**)&nrm, g_nrm);
    cudaGetSymbolAddress((void**)&qkv, g_qkv);
    cudaGetSymbolAddress((void**)&ekv, g_ekv);
    cudaGetSymbolAddress((void**)&att, g_att);

    // 1. GroupNorm
    gn_kernel<<<B_ * GROUPS_, 256>>>(x, gamma, beta, nrm);

    // 2. qkv projection: [8] x (1536x512 @ 512x1024)
    gemm_kernel<<<dim3(8, 12, B_), 256>>>(qkv_w, nrm, qkv_b, nullptr, qkv,
        1536, 1024, 512, T_, (long long)C_ * T_, T_, (long long)3 * C_ * T_);

    // 3. encoder kv: [8] x (1024x512 @ 512x77)
    gemm_kernel<<<dim3(1, 8, B_), 256>>>(ekv_w, enc, ekv_b, nullptr, ekv,
        1024, S_, 512, S_, (long long)C_ * S_, S_, (long long)2 * C_ * S_);

    // 4. flash attention over 64 heads x 16 query tiles
    int smem = (4 * 64 * PAD + 3 * 64 + 80) * (int)sizeof(float);
    cudaFuncSetAttribute(attn_kernel, cudaFuncAttributeMaxDynamicSharedMemorySize, smem);
    attn_kernel<<<dim3(16, 64), 256, smem>>>(mask);

    // 5. output projection + bias + residual -> d_out
    gemm_kernel<<<dim3(8, 4, B_), 256>>>(proj_w, att, proj_b, x, out,
        512, 1024, 512, T_, (long long)C_ * T_, T_, (long long)C_ * T_);
}

// round 3
// speedup vs baseline: 2.1576x; 2.1576x over previous
#include <cuda_runtime.h>
#include <cstdint>

#define B_      8
#define C_      512
#define T_      1024
#define HEADS_  8
#define CH_     64
#define S_      77
#define L_      1101
#define GROUPS_ 32
#define CPG_    16

// Scratch (static device globals; no dynamic allocation allowed)
static __device__ float g_nrm[B_ * C_ * T_];
static __device__ float g_qkv[B_ * 3 * C_ * T_];
static __device__ float g_ekv[B_ * 2 * C_ * S_];
static __device__ float g_att[B_ * C_ * T_];

// ---------------------------------------------------------------------------
// tf32 helpers (portable PTX, no arch-suffix features)
// ---------------------------------------------------------------------------
__device__ __forceinline__ float tf32r(float f) {
    uint32_t u;
    asm("cvt.rna.tf32.f32 %0, %1;" : "=r"(u) : "f"(f));
    return __uint_as_float(u);
}
__device__ __forceinline__ void mma_tf32(float* c, const uint32_t* a, const uint32_t* b) {
    asm volatile("mma.sync.aligned.m16n8k8.row.col.f32.tf32.tf32.f32 "
        "{%0,%1,%2,%3}, {%4,%5,%6,%7}, {%8,%9}, {%0,%1,%2,%3};"
        : "+f"(c[0]), "+f"(c[1]), "+f"(c[2]), "+f"(c[3])
        : "r"(a[0]), "r"(a[1]), "r"(a[2]), "r"(a[3]), "r"(b[0]), "r"(b[1]));
}

// ---------------------------------------------------------------------------
// GroupNorm32
// ---------------------------------------------------------------------------
__global__ __launch_bounds__(256) void gn_kernel(
    const float* __restrict__ x, const float* __restrict__ gamma,
    const float* __restrict__ beta, float* __restrict__ out)
{
    int b = blockIdx.x / GROUPS_, g = blockIdx.x % GROUPS_;
    const float* xp = x + ((size_t)b * C_ + g * CPG_) * T_;
    float* op = out + ((size_t)b * C_ + g * CPG_) * T_;
    const int N = CPG_ * T_;

    float s = 0.f, q = 0.f;
    for (int i = threadIdx.x; i < N; i += 256) {
        float v = xp[i];
        s += v; q = fmaf(v, v, q);
    }
    __shared__ float rs[256], rq[256];
    rs[threadIdx.x] = s; rq[threadIdx.x] = q;
    __syncthreads();
    for (int o = 128; o > 0; o >>= 1) {
        if (threadIdx.x < o) { rs[threadIdx.x] += rs[threadIdx.x + o]; rq[threadIdx.x] += rq[threadIdx.x + o]; }
        __syncthreads();
    }
    float mean = rs[0] * (1.f / N);
    float var  = rq[0] * (1.f / N) - mean * mean;
    float inv  = rsqrtf(var + 1e-5f);
    for (int i = threadIdx.x; i < N; i += 256) {
        int c = g * CPG_ + (i >> 10);
        op[i] = (xp[i] - mean) * inv * gamma[c] + beta[c];
    }
}

// ---------------------------------------------------------------------------
// tf32 tensor-core GEMM: C[z][m][n] = A[m][:] . B[z][:][n] + bias[m] (+res)
// 128x128 tile, 8 warps (2x4), warp tile 64x32, m16n8k8. M%128==0, K%16==0.
// ---------------------------------------------------------------------------
__global__ __launch_bounds__(256, 2) void gemm_tc(
    const float* __restrict__ A, const float* __restrict__ Bm,
    const float* __restrict__ bias, const float* __restrict__ res,
    float* __restrict__ Cm, int M, int N, int K,
    int ldb, long long sB, int ldc, long long sC)
{
    __shared__ float As[16][132];   // [k][m]
    __shared__ float Bs[16][132];   // [k][n]

    const float* Bp = Bm + (size_t)blockIdx.z * sB;
    float* Cp = Cm + (size_t)blockIdx.z * sC;
    const float* Rp = res ? (res + (size_t)blockIdx.z * sC) : nullptr;

    int bm = blockIdx.y << 7, bn = blockIdx.x << 7;
    int tid = threadIdx.x, wid = tid >> 5, lane = tid & 31;
    int wm = (wid >> 2) << 6, wn = (wid & 3) << 5;
    int gr = lane >> 2, gc = lane & 3;

    float c[4][4][4];
#pragma unroll
    for (int i = 0; i < 4; i++)
#pragma unroll
        for (int j = 0; j < 4; j++)
#pragma unroll
            for (int l = 0; l < 4; l++) c[i][j][l] = 0.f;

    for (int k0 = 0; k0 < K; k0 += 16) {
#pragma unroll
        for (int l = 0; l < 8; l++) {
            int idx = tid + (l << 8);
            As[idx & 15][idx >> 4] = tf32r(A[(size_t)(bm + (idx >> 4)) * K + k0 + (idx & 15)]);
        }
#pragma unroll
        for (int l = 0; l < 8; l++) {
            int idx = tid + (l << 8);
            int n = idx & 127, k = idx >> 7;
            int gn = bn + n;
            Bs[k][n] = (gn < N) ? tf32r(Bp[(size_t)(k0 + k) * ldb + gn]) : 0.f;
        }
        __syncthreads();
#pragma unroll
        for (int kk = 0; kk < 16; kk += 8) {
            uint32_t af[4][4], bf[4][2];
#pragma unroll
            for (int mt = 0; mt < 4; mt++) {
                int m = wm + (mt << 4);
                af[mt][0] = __float_as_uint(As[kk + gc][m + gr]);
                af[mt][1] = __float_as_uint(As[kk + gc][m + 8 + gr]);
                af[mt][2] = __float_as_uint(As[kk + 4 + gc][m + gr]);
                af[mt][3] = __float_as_uint(As[kk + 4 + gc][m + 8 + gr]);
            }
#pragma unroll
            for (int nt = 0; nt < 4; nt++) {
                int n = wn + (nt << 3);
                bf[nt][0] = __float_as_uint(Bs[kk + gc][n + gr]);
                bf[nt][1] = __float_as_uint(Bs[kk + 4 + gc][n + gr]);
            }
#pragma unroll
            for (int mt = 0; mt < 4; mt++)
#pragma unroll
                for (int nt = 0; nt < 4; nt++)
                    mma_tf32(c[mt][nt], af[mt], bf[nt]);
        }
        __syncthreads();
    }

#pragma unroll
    for (int mt = 0; mt < 4; mt++) {
        int m0 = bm + wm + (mt << 4) + gr;
        float bv0 = bias[m0], bv1 = bias[m0 + 8];
#pragma unroll
        for (int nt = 0; nt < 4; nt++) {
            int n = bn + wn + (nt << 3) + (gc << 1);
            if (n < N) {
                float v0 = c[mt][nt][0] + bv0;
                float v2 = c[mt][nt][2] + bv1;
                if (Rp) { v0 += Rp[(size_t)m0 * ldc + n]; v2 += Rp[(size_t)(m0 + 8) * ldc + n]; }
                Cp[(size_t)m0 * ldc + n] = v0;
                Cp[(size_t)(m0 + 8) * ldc + n] = v2;
            }
            if (n + 1 < N) {
                float v1 = c[mt][nt][1] + bv0;
                float v3 = c[mt][nt][3] + bv1;
                if (Rp) { v1 += Rp[(size_t)m0 * ldc + n + 1]; v3 += Rp[(size_t)(m0 + 8) * ldc + n + 1]; }
                Cp[(size_t)m0 * ldc + n + 1] = v1;
                Cp[(size_t)(m0 + 8) * ldc + n + 1] = v3;
            }
        }
    }
}

// ---------------------------------------------------------------------------
// tf32 mma.sync flash attention (softmax-without-max; O accum in registers).
// CTA = 128 queries x 1 head; 8 warps, each owns a 16-query band.
// smem floats: Ks[64][68], Vs[64][68], Ps[128][68], madd[1152]
// ---------------------------------------------------------------------------
#define KS_OFF  0
#define VS_OFF  (64 * 68)
#define PS_OFF  (2 * 64 * 68)
#define MADD_OFF (PS_OFF + 128 * 68)
#define ATT_SMEM ((MADD_OFF + 1152) * 4)

__global__ __launch_bounds__(256, 2) void attn_tc_kernel(const unsigned int* __restrict__ mask)
{
    extern __shared__ float sm[];
    float* Ks = sm + KS_OFF;
    float* Vs = sm + VS_OFF;
    float* Ps = sm + PS_OFF;
    float* madd = sm + MADD_OFF;

    int tid = threadIdx.x, wid = tid >> 5, lane = tid & 31;
    int gr = lane >> 2, gc = lane & 3;
    int bh = blockIdx.y, b = bh >> 3, h = bh & 7;
    int t0 = blockIdx.x << 7;
    int r0 = (wid << 4) + gr;           // this thread's first query row (band-local 0..127)

    const float* qb  = g_qkv + ((size_t)b * 3 * C_ + h * 192) * T_ + t0;
    const float* kb  = g_qkv + ((size_t)b * 3 * C_ + h * 192 + 64) * T_;
    const float* vb  = g_qkv + ((size_t)b * 3 * C_ + h * 192 + 128) * T_;
    const float* keb = g_ekv + ((size_t)b * 2 * C_ + h * 128) * S_;
    const float* veb = g_ekv + ((size_t)b * 2 * C_ + h * 128 + 64) * S_;

    // additive mask over padded L; torch.tile head-major quirk: mask row = h
    for (int s = tid; s < 1152; s += 256)
        madd[s] = (s < S_) ? (mask[h * S_ + s] ? 0.f : -10000.f)
                           : ((s < L_) ? 0.f : -1e30f);

    // stage Q [128t][64ch] into Ps, scaled by 1/8 (= scale^2, exact), tf32-rounded
    for (int i = tid; i < 8192; i += 256) {
        int ch = i >> 7, t = i & 127;
        Ps[t * 68 + ch] = tf32r(qb[(size_t)ch * T_ + t] * 0.125f);
    }
    __syncthreads();

    // Q fragments live in registers for the whole kernel
    uint32_t qf[8][4];
#pragma unroll
    for (int kt = 0; kt < 8; kt++) {
        qf[kt][0] = __float_as_uint(Ps[r0 * 68 + (kt << 3) + gc]);
        qf[kt][1] = __float_as_uint(Ps[(r0 + 8) * 68 + (kt << 3) + gc]);
        qf[kt][2] = __float_as_uint(Ps[r0 * 68 + (kt << 3) + 4 + gc]);
        qf[kt][3] = __float_as_uint(Ps[(r0 + 8) * 68 + (kt << 3) + 4 + gc]);
    }
    __syncthreads();

    float o[8][4];
#pragma unroll
    for (int nt = 0; nt < 8; nt++)
#pragma unroll
        for (int l = 0; l < 4; l++) o[nt][l] = 0.f;
    float lsum0 = 0.f, lsum1 = 0.f;

    for (int c0 = 0; c0 < L_; c0 += 64) {
        // load K chunk [s][ch] and V^T chunk [s][ch]
        for (int i = tid; i < 4096; i += 256) {
            int ch = i >> 6, sl = i & 63, s = c0 + sl;
            float kv = 0.f, vv = 0.f;
            if (s < S_)      { kv = keb[ch * S_ + s]; vv = veb[ch * S_ + s]; }
            else if (s < L_) { kv = kb[(size_t)ch * T_ + s - S_]; vv = vb[(size_t)ch * T_ + s - S_]; }
            Ks[sl * 68 + ch] = tf32r(kv);
            Vs[sl * 68 + ch] = tf32r(vv);
        }
        __syncthreads();

        // MMA1: S[16-band, 64s] = Q . K^T
        float s8[8][4];
#pragma unroll
        for (int nt = 0; nt < 8; nt++)
#pragma unroll
            for (int l = 0; l < 4; l++) s8[nt][l] = 0.f;
#pragma unroll
        for (int kt = 0; kt < 8; kt++) {
#pragma unroll
            for (int nt = 0; nt < 8; nt++) {
                uint32_t bf[2];
                bf[0] = __float_as_uint(Ks[((nt << 3) + gr) * 68 + (kt << 3) + gc]);
                bf[1] = __float_as_uint(Ks[((nt << 3) + gr) * 68 + (kt << 3) + 4 + gc]);
                mma_tf32(s8[nt], qf[kt], bf);
            }
        }

        // softmax (no running max) in registers; row sums accumulated per thread
#pragma unroll
        for (int nt = 0; nt < 8; nt++) {
            int col = c0 + (nt << 3) + (gc << 1);
            float m0 = madd[col], m1 = madd[col + 1];
            float p0 = __expf(s8[nt][0] + m0);
            float p1 = __expf(s8[nt][1] + m1);
            float p2 = __expf(s8[nt][2] + m0);
            float p3 = __expf(s8[nt][3] + m1);
            lsum0 += p0 + p1; lsum1 += p2 + p3;
            int pc = (nt << 3) + (gc << 1);
            *(float2*)&Ps[r0 * 68 + pc]       = make_float2(p0, p1);
            *(float2*)&Ps[(r0 + 8) * 68 + pc] = make_float2(p2, p3);
        }
        __syncwarp();

        // MMA2: O[16-band, 64ch] += P . V^T   (P rows are warp-private)
#pragma unroll
        for (int kt = 0; kt < 8; kt++) {
            uint32_t af[4];
            af[0] = __float_as_uint(Ps[r0 * 68 + (kt << 3) + gc]);
            af[1] = __float_as_uint(Ps[(r0 + 8) * 68 + (kt << 3) + gc]);
            af[2] = __float_as_uint(Ps[r0 * 68 + (kt << 3) + 4 + gc]);
            af[3] = __float_as_uint(Ps[(r0 + 8) * 68 + (kt << 3) + 4 + gc]);
#pragma unroll
            for (int nt = 0; nt < 8; nt++) {
                uint32_t bf[2];
                bf[0] = __float_as_uint(Vs[((kt << 3) + gc) * 68 + (nt << 3) + gr]);
                bf[1] = __float_as_uint(Vs[((kt << 3) + 4 + gc) * 68 + (nt << 3) + gr]);
                mma_tf32(o[nt], af, bf);
            }
        }
        __syncthreads();
    }

    // reduce row sums across the 4 lanes sharing each row
    lsum0 += __shfl_xor_sync(0xffffffffu, lsum0, 1);
    lsum0 += __shfl_xor_sync(0xffffffffu, lsum0, 2);
    lsum1 += __shfl_xor_sync(0xffffffffu, lsum1, 1);
    lsum1 += __shfl_xor_sync(0xffffffffu, lsum1, 2);
    float inv0 = 1.f / lsum0, inv1 = 1.f / lsum1;

    // transpose O to [ch][t] via smem (reuse Ks/Vs region), then coalesced store
    float* tr = sm;   // [64][132]
#pragma unroll
    for (int nt = 0; nt < 8; nt++) {
        int ch = (nt << 3) + (gc << 1);
        tr[ch * 132 + r0]           = o[nt][0] * inv0;
        tr[(ch + 1) * 132 + r0]     = o[nt][1] * inv0;
        tr[ch * 132 + r0 + 8]       = o[nt][2] * inv1;
        tr[(ch + 1) * 132 + r0 + 8] = o[nt][3] * inv1;
    }
    __syncthreads();
    float* ob = g_att + ((size_t)b * C_ + h * CH_) * T_ + t0;
    for (int i = tid; i < 8192; i += 256) {
        int ch = i >> 7, t = i & 127;
        ob[(size_t)ch * T_ + t] = tr[ch * 132 + t];
    }
}

// ---------------------------------------------------------------------------
extern "C" void kernel_launch(void* const* d_in, const int* in_sizes, int n_in,
                              void* d_out, int out_size)
{
    (void)in_sizes; (void)n_in; (void)out_size;
    const float* x       = (const float*)d_in[0];
    const float* enc     = (const float*)d_in[1];
    const unsigned int* mask = (const unsigned int*)d_in[2];
    const float* gamma   = (const float*)d_in[3];
    const float* beta    = (const float*)d_in[4];
    const float* qkv_w   = (const float*)d_in[5];
    const float* qkv_b   = (const float*)d_in[6];
    const float* ekv_w   = (const float*)d_in[7];
    const float* ekv_b   = (const float*)d_in[8];
    const float* proj_w  = (const float*)d_in[9];
    const float* proj_b  = (const float*)d_in[10];
    float* out = (float*)d_out;

    float *nrm, *qkv, *ekv, *att;
    cudaGetSymbolAddress((void**)&nrm, g_nrm);
    cudaGetSymbolAddress((void**)&qkv, g_qkv);
    cudaGetSymbolAddress((void**)&ekv, g_ekv);
    cudaGetSymbolAddress((void**)&att, g_att);

    // 1. GroupNorm
    gn_kernel<<<B_ * GROUPS_, 256>>>(x, gamma, beta, nrm);

    // 2. qkv projection: [8] x (1536x512 @ 512x1024)
    gemm_tc<<<dim3(8, 12, B_), 256>>>(qkv_w, nrm, qkv_b, nullptr, qkv,
        1536, 1024, 512, T_, (long long)C_ * T_, T_, (long long)3 * C_ * T_);

    // 3. encoder kv: [8] x (1024x512 @ 512x77)
    gemm_tc<<<dim3(1, 8, B_), 256>>>(ekv_w, enc, ekv_b, nullptr, ekv,
        1024, S_, 512, S_, (long long)C_ * S_, S_, (long long)2 * C_ * S_);

    // 4. tf32 mma attention: 64 bh x 8 q-tiles of 128
    cudaFuncSetAttribute(attn_tc_kernel, cudaFuncAttributeMaxDynamicSharedMemorySize, ATT_SMEM);
    attn_tc_kernel<<<dim3(8, 64), 256, ATT_SMEM>>>(mask);

    // 5. output projection + bias + residual -> d_out
    gemm_tc<<<dim3(8, 4, B_), 256>>>(proj_w, att, proj_b, x, out,
        512, 1024, 512, T_, (long long)C_ * T_, T_, (long long)C_ * T_);
}

// round 6
// speedup vs baseline: 3.6199x; 1.6777x over previous
#include <cuda_runtime.h>
#include <cuda_bf16.h>
#include <cstdint>

#define B_      8
#define C_      512
#define T_      1024
#define HEADS_  8
#define CH_     64
#define S_      77
#define L_      1101
#define LP_     1152
#define GROUPS_ 32
#define CPG_    16

// Scratch (static device globals; zero-initialized at load)
static __device__ float g_nrm[B_ * C_ * T_];
static __device__ float g_att[B_ * C_ * T_];
static __device__ __nv_bfloat16 g_qp[B_ * HEADS_ * CH_ * T_];   // [bh][ch][t], pre-scaled 1/8
static __device__ __nv_bfloat16 g_kp[B_ * HEADS_ * CH_ * LP_];  // [bh][ch][0:1024 self | 1024:1101 enc | pad0]
static __device__ __nv_bfloat16 g_vp[B_ * HEADS_ * CH_ * LP_];

// ---------------------------------------------------------------------------
// PTX helpers (portable, no sm_103a-suffix features)
// ---------------------------------------------------------------------------
__device__ __forceinline__ uint32_t smem_u32(const void* p) {
    uint32_t a;
    asm("{ .reg .u64 t; cvta.to.shared.u64 t, %1; cvt.u32.u64 %0, t; }" : "=r"(a) : "l"(p));
    return a;
}
__device__ __forceinline__ float tf32r(float f) {
    uint32_t u;
    asm("cvt.rna.tf32.f32 %0, %1;" : "=r"(u) : "f"(f));
    return __uint_as_float(u);
}
__device__ __forceinline__ void mma_tf32(float* c, const uint32_t* a, const uint32_t* b) {
    asm volatile("mma.sync.aligned.m16n8k8.row.col.f32.tf32.tf32.f32 "
        "{%0,%1,%2,%3}, {%4,%5,%6,%7}, {%8,%9}, {%0,%1,%2,%3};"
        : "+f"(c[0]), "+f"(c[1]), "+f"(c[2]), "+f"(c[3])
        : "r"(a[0]), "r"(a[1]), "r"(a[2]), "r"(a[3]), "r"(b[0]), "r"(b[1]));
}
__device__ __forceinline__ void mma_bf16(float* c, const uint32_t* a, const uint32_t* b) {
    asm volatile("mma.sync.aligned.m16n8k16.row.col.f32.bf16.bf16.f32 "
        "{%0,%1,%2,%3}, {%4,%5,%6,%7}, {%8,%9}, {%0,%1,%2,%3};"
        : "+f"(c[0]), "+f"(c[1]), "+f"(c[2]), "+f"(c[3])
        : "r"(a[0]), "r"(a[1]), "r"(a[2]), "r"(a[3]), "r"(b[0]), "r"(b[1]));
}
__device__ __forceinline__ void ldsm4(uint32_t* r, uint32_t a) {
    asm volatile("ldmatrix.sync.aligned.m8n8.x4.shared.b16 {%0,%1,%2,%3}, [%4];"
        : "=r"(r[0]), "=r"(r[1]), "=r"(r[2]), "=r"(r[3]) : "r"(a));
}
__device__ __forceinline__ void ldsm4t(uint32_t* r, uint32_t a) {
    asm volatile("ldmatrix.sync.aligned.m8n8.x4.trans.shared.b16 {%0,%1,%2,%3}, [%4];"
        : "=r"(r[0]), "=r"(r[1]), "=r"(r[2]), "=r"(r[3]) : "r"(a));
}
__device__ __forceinline__ void cp16(uint32_t dst, const void* src) {
    asm volatile("cp.async.cg.shared.global [%0], [%1], 16;" :: "r"(dst), "l"(src));
}
#define CP_COMMIT() asm volatile("cp.async.commit_group;" ::: "memory")
#define CP_WAIT1()  asm volatile("cp.async.wait_group 1;" ::: "memory")

__device__ __forceinline__ __nv_bfloat162 pack2(float a, float b) {
    __nv_bfloat162 w;
    w.x = __float2bfloat16_rn(a);
    w.y = __float2bfloat16_rn(b);
    return w;
}

// ---------------------------------------------------------------------------
// GroupNorm32
// ---------------------------------------------------------------------------
__global__ __launch_bounds__(256) void gn_kernel(
    const float* __restrict__ x, const float* __restrict__ gamma,
    const float* __restrict__ beta, float* __restrict__ out)
{
    int b = blockIdx.x / GROUPS_, g = blockIdx.x % GROUPS_;
    const float* xp = x + ((size_t)b * C_ + g * CPG_) * T_;
    float* op = out + ((size_t)b * C_ + g * CPG_) * T_;
    const int N = CPG_ * T_;

    float s = 0.f, q = 0.f;
    for (int i = threadIdx.x; i < N; i += 256) {
        float v = xp[i];
        s += v; q = fmaf(v, v, q);
    }
    __shared__ float rs[256], rq[256];
    rs[threadIdx.x] = s; rq[threadIdx.x] = q;
    __syncthreads();
    for (int o = 128; o > 0; o >>= 1) {
        if (threadIdx.x < o) { rs[threadIdx.x] += rs[threadIdx.x + o]; rq[threadIdx.x] += rq[threadIdx.x + o]; }
        __syncthreads();
    }
    float mean = rs[0] * (1.f / N);
    float var  = rq[0] * (1.f / N) - mean * mean;
    float inv  = rsqrtf(var + 1e-5f);
    for (int i = threadIdx.x; i < N; i += 256) {
        int c = g * CPG_ + (i >> 10);
        op[i] = (xp[i] - mean) * inv * gamma[c] + beta[c];
    }
}

// ---------------------------------------------------------------------------
// tf32 tensor-core GEMM + flexible epilogue.
// mode 0: fp32 C + bias (+res). mode 1: qkv -> bf16 packs (q scaled 1/8).
// mode 2: ekv -> bf16 packs at column 1024+n.
// Row decode is HEAD-MAJOR per the reference reshape:
//   mode 1: m = h*192 + type*64 + ch   (type 0=q,1=k,2=v)
//   mode 2: m = h*128 + type*64 + ch   (type 0=ek,1=ev)
// ---------------------------------------------------------------------------
__device__ __forceinline__ void write_pack(int mode, int z, int m, int n, float v0, float v1, int N) {
    int h, type, ch;
    if (mode == 1) {
        h = m / 192;
        int sub = m - h * 192;
        type = sub >> 6; ch = sub & 63;
    } else {
        h = m >> 7;
        type = (m >> 6) & 1; ch = m & 63;
    }
    size_t row = (size_t)(z * 8 + h) * 64 + ch;
    if (mode == 1) {
        if (type == 0) {
            *(__nv_bfloat162*)&g_qp[row * T_ + n] = pack2(v0 * 0.125f, v1 * 0.125f);
        } else {
            __nv_bfloat16* p = (type == 1 ? g_kp : g_vp) + row * LP_ + n;
            *(__nv_bfloat162*)p = pack2(v0, v1);
        }
    } else {
        __nv_bfloat16* p = (type == 0 ? g_kp : g_vp) + row * LP_ + 1024 + n;
        if (n + 1 < N)      *(__nv_bfloat162*)p = pack2(v0, v1);
        else if (n < N)     *p = __float2bfloat16_rn(v0);
    }
}

__global__ __launch_bounds__(256, 2) void gemm_tc(
    const float* __restrict__ A, const float* __restrict__ Bm,
    const float* __restrict__ bias, const float* __restrict__ res,
    float* __restrict__ Cm, int M, int N, int K,
    int ldb, long long sB, int ldc, long long sC, int mode)
{
    __shared__ float As[16][132];
    __shared__ float Bs[16][132];

    const float* Bp = Bm + (size_t)blockIdx.z * sB;
    int bm = blockIdx.y << 7, bn = blockIdx.x << 7;
    int tid = threadIdx.x, wid = tid >> 5, lane = tid & 31;
    int wm = (wid >> 2) << 6, wn = (wid & 3) << 5;
    int gr = lane >> 2, gc = lane & 3;

    float c[4][4][4];
#pragma unroll
    for (int i = 0; i < 4; i++)
#pragma unroll
        for (int j = 0; j < 4; j++)
#pragma unroll
            for (int l = 0; l < 4; l++) c[i][j][l] = 0.f;

    for (int k0 = 0; k0 < K; k0 += 16) {
#pragma unroll
        for (int l = 0; l < 8; l++) {
            int idx = tid + (l << 8);
            As[idx & 15][idx >> 4] = tf32r(A[(size_t)(bm + (idx >> 4)) * K + k0 + (idx & 15)]);
        }
#pragma unroll
        for (int l = 0; l < 8; l++) {
            int idx = tid + (l << 8);
            int n = idx & 127, k = idx >> 7;
            int gn = bn + n;
            Bs[k][n] = (gn < N) ? tf32r(Bp[(size_t)(k0 + k) * ldb + gn]) : 0.f;
        }
        __syncthreads();
#pragma unroll
        for (int kk = 0; kk < 16; kk += 8) {
            uint32_t af[4][4], bf[4][2];
#pragma unroll
            for (int mt = 0; mt < 4; mt++) {
                int m = wm + (mt << 4);
                af[mt][0] = __float_as_uint(As[kk + gc][m + gr]);
                af[mt][1] = __float_as_uint(As[kk + gc][m + 8 + gr]);
                af[mt][2] = __float_as_uint(As[kk + 4 + gc][m + gr]);
                af[mt][3] = __float_as_uint(As[kk + 4 + gc][m + 8 + gr]);
            }
#pragma unroll
            for (int nt = 0; nt < 4; nt++) {
                int n = wn + (nt << 3);
                bf[nt][0] = __float_as_uint(Bs[kk + gc][n + gr]);
                bf[nt][1] = __float_as_uint(Bs[kk + 4 + gc][n + gr]);
            }
#pragma unroll
            for (int mt = 0; mt < 4; mt++)
#pragma unroll
                for (int nt = 0; nt < 4; nt++)
                    mma_tf32(c[mt][nt], af[mt], bf[nt]);
        }
        __syncthreads();
    }

    float* Cp = Cm ? (Cm + (size_t)blockIdx.z * sC) : nullptr;
    const float* Rp = res ? (res + (size_t)blockIdx.z * sC) : nullptr;

#pragma unroll
    for (int mt = 0; mt < 4; mt++) {
        int m0 = bm + wm + (mt << 4) + gr;
        float bv0 = bias[m0], bv1 = bias[m0 + 8];
#pragma unroll
        for (int nt = 0; nt < 4; nt++) {
            int n = bn + wn + (nt << 3) + (gc << 1);
            float v0 = c[mt][nt][0] + bv0, v1 = c[mt][nt][1] + bv0;
            float v2 = c[mt][nt][2] + bv1, v3 = c[mt][nt][3] + bv1;
            if (mode == 0) {
                if (n < N) {
                    float a0 = v0, a2 = v2;
                    if (Rp) { a0 += Rp[(size_t)m0 * ldc + n]; a2 += Rp[(size_t)(m0 + 8) * ldc + n]; }
                    Cp[(size_t)m0 * ldc + n] = a0;
                    Cp[(size_t)(m0 + 8) * ldc + n] = a2;
                }
                if (n + 1 < N) {
                    float a1 = v1, a3 = v3;
                    if (Rp) { a1 += Rp[(size_t)m0 * ldc + n + 1]; a3 += Rp[(size_t)(m0 + 8) * ldc + n + 1]; }
                    Cp[(size_t)m0 * ldc + n + 1] = a1;
                    Cp[(size_t)(m0 + 8) * ldc + n + 1] = a3;
                }
            } else {
                write_pack(mode, blockIdx.z, m0, n, v0, v1, N);
                write_pack(mode, blockIdx.z, m0 + 8, n, v2, v3, N);
            }
        }
    }
}

// ---------------------------------------------------------------------------
// bf16 mma.sync flash attention, ldmatrix fragments, cp.async double buffer.
// CTA = 128 queries x head; 8 warps x 16-query bands; 18 chunks of 64 keys.
// smem map (bytes): QS 0..16K, KS 16K..32K (2x8K), VS 32K..48K (2x8K),
//                   PS 49152..65536 (16K), MADD 65536..70144
// ---------------------------------------------------------------------------
#define QS_OFF   0
#define KS_OFF   16384
#define VS_OFF   32768
#define PS_OFF   49152
#define MADD_OFF 65536
#define ATT_SMEM 70144

__device__ __forceinline__ void prefetch_kv(uint32_t sbase,
    const __nv_bfloat16* Kg, const __nv_bfloat16* Vg, int c, int buf, int tid)
{
#pragma unroll
    for (int j = 0; j < 4; j++) {
        int i = tid + (j << 8);
        int sel = i >> 9, ch = (i >> 3) & 63, seg = i & 7;
        const __nv_bfloat16* src = (sel ? Vg : Kg) + ch * LP_ + (c << 6) + (seg << 3);
        uint32_t dst = sbase + (sel ? VS_OFF : KS_OFF) + (buf << 13)
                     + (ch << 7) + ((seg ^ (ch & 7)) << 4);
        cp16(dst, src);
    }
}

__global__ __launch_bounds__(256, 2) void attn_bf16_kernel(const unsigned int* __restrict__ mask)
{
    extern __shared__ char smc[];
    const uint32_t sbase = smem_u32(smc);
    int tid = threadIdx.x, lane = tid & 31, wid = tid >> 5;
    int gr = lane >> 2, gc = lane & 3, l7 = lane & 7, g = lane >> 3;
    int bh = blockIdx.y, h = bh & 7;
    int t0 = blockIdx.x << 7;
    int r0w = wid << 4;

    const __nv_bfloat16* Qg = g_qp + (size_t)bh * 64 * T_;
    const __nv_bfloat16* Kg = g_kp + (size_t)bh * 64 * LP_;
    const __nv_bfloat16* Vg = g_vp + (size_t)bh * 64 * LP_;

    // additive mask: self cols [0,1024) = 0, encoder [1024,1101) masked, pad = -inf
    float* madd = (float*)(smc + MADD_OFF);
    for (int s = tid; s < LP_; s += 256)
        madd[s] = (s < 1024) ? 0.f
                : (s < L_ ? (mask[h * S_ + (s - 1024)] ? 0.f : -10000.f) : -1e30f);

    // Q tile [64ch][128t] bf16, swizzled 16B chunks
    for (int i = tid; i < 1024; i += 256) {
        int ch = i >> 4, seg = i & 15;
        uint4 v = *(const uint4*)(Qg + ch * T_ + t0 + seg * 8);
        *(uint4*)(smc + QS_OFF + ch * 256 + ((seg ^ (ch & 7)) << 4)) = v;
    }
    __syncthreads();

    // Q fragments (trans ldmatrix): qf[kt] covers k = ch [kt*16, kt*16+16)
    uint32_t qf[4][4];
#pragma unroll
    for (int kt = 0; kt < 4; kt++) {
        int ch = kt * 16 + l7 + ((g >> 1) << 3);
        int tb = (r0w << 1) + ((g & 1) << 4);
        ldsm4t(qf[kt], sbase + QS_OFF + ch * 256 + (tb ^ ((ch & 7) << 4)));
    }

    float o[8][4];
#pragma unroll
    for (int nt = 0; nt < 8; nt++)
#pragma unroll
        for (int l = 0; l < 4; l++) o[nt][l] = 0.f;
    float lsum0 = 0.f, lsum1 = 0.f;

    prefetch_kv(sbase, Kg, Vg, 0, 0, tid); CP_COMMIT();
    prefetch_kv(sbase, Kg, Vg, 1, 1, tid); CP_COMMIT();

    for (int c = 0; c < 18; c++) {
        CP_WAIT1();
        __syncthreads();
        int buf = c & 1;
        uint32_t kb = sbase + KS_OFF + (buf << 13);
        uint32_t vb = sbase + VS_OFF + (buf << 13);

        // MMA1: S[16-band, 64s] = Q . K^T
        float s8[8][4];
#pragma unroll
        for (int nt = 0; nt < 8; nt++)
#pragma unroll
            for (int l = 0; l < 4; l++) s8[nt][l] = 0.f;
#pragma unroll
        for (int kt = 0; kt < 4; kt++) {
            int ch = kt * 16 + l7 + ((g & 1) << 3);
#pragma unroll
            for (int ntp = 0; ntp < 4; ntp++) {
                uint32_t bf4[4];
                int seg = ntp * 2 + (g >> 1);
                ldsm4t(bf4, kb + (ch << 7) + ((seg ^ (ch & 7)) << 4));
                mma_bf16(s8[ntp * 2],     qf[kt], bf4);
                mma_bf16(s8[ntp * 2 + 1], qf[kt], bf4 + 2);
            }
        }

        // softmax (no running max; scores are small by construction)
        int colb = c << 6;
#pragma unroll
        for (int nt = 0; nt < 8; nt++) {
            int col = colb + nt * 8 + gc * 2;
            float m0 = madd[col], m1 = madd[col + 1];
            float p0 = __expf(s8[nt][0] + m0), p1 = __expf(s8[nt][1] + m1);
            float p2 = __expf(s8[nt][2] + m0), p3 = __expf(s8[nt][3] + m1);
            lsum0 += p0 + p1; lsum1 += p2 + p3;
            int row0 = r0w + gr, row1 = row0 + 8;
            *(__nv_bfloat162*)(smc + PS_OFF + row0 * 128 + ((nt ^ (row0 & 7)) << 4) + gc * 4) = pack2(p0, p1);
            *(__nv_bfloat162*)(smc + PS_OFF + row1 * 128 + ((nt ^ (row1 & 7)) << 4) + gc * 4) = pack2(p2, p3);
        }
        __syncwarp();

        // MMA2: O[16-band, 64ch] += P . V^T
#pragma unroll
        for (int kt = 0; kt < 4; kt++) {
            uint32_t af[4];
            int row = r0w + l7 + ((g & 1) << 3);
            int pseg = kt * 2 + (g >> 1);
            ldsm4(af, sbase + PS_OFF + (row << 7) + ((pseg ^ (row & 7)) << 4));
#pragma unroll
            for (int ntp = 0; ntp < 4; ntp++) {
                uint32_t bv4[4];
                int ch = (ntp * 2 + (g >> 1)) * 8 + l7;
                int sseg = kt * 2 + (g & 1);
                ldsm4(bv4, vb + (ch << 7) + ((sseg ^ (ch & 7)) << 4));
                mma_bf16(o[ntp * 2],     af, bv4);
                mma_bf16(o[ntp * 2 + 1], af, bv4 + 2);
            }
        }
        __syncthreads();
        if (c + 2 < 18) prefetch_kv(sbase, Kg, Vg, c + 2, buf, tid);
        CP_COMMIT();
    }

    // row-sum reduce over the 4 lanes of each row
    lsum0 += __shfl_xor_sync(0xffffffffu, lsum0, 1);
    lsum0 += __shfl_xor_sync(0xffffffffu, lsum0, 2);
    lsum1 += __shfl_xor_sync(0xffffffffu, lsum1, 1);
    lsum1 += __shfl_xor_sync(0xffffffffu, lsum1, 2);
    float inv0 = 1.f / lsum0, inv1 = 1.f / lsum1;

    // transpose O to [ch][t] via smem, coalesced store
    float* tr = (float*)smc;   // [64][132] floats = 33792 B, reuses Q/K region
    int r0g = r0w + gr;
#pragma unroll
    for (int nt = 0; nt < 8; nt++) {
        int ch = nt * 8 + gc * 2;
        tr[ch * 132 + r0g]           = o[nt][0] * inv0;
        tr[(ch + 1) * 132 + r0g]     = o[nt][1] * inv0;
        tr[ch * 132 + r0g + 8]       = o[nt][2] * inv1;
        tr[(ch + 1) * 132 + r0g + 8] = o[nt][3] * inv1;
    }
    __syncthreads();
    float* ob = g_att + ((size_t)(bh >> 3) * C_ + h * CH_) * T_ + t0;
    for (int i = tid; i < 8192; i += 256) {
        int ch = i >> 7, t = i & 127;
        ob[(size_t)ch * T_ + t] = tr[ch * 132 + t];
    }
}

// ---------------------------------------------------------------------------
extern "C" void kernel_launch(void* const* d_in, const int* in_sizes, int n_in,
                              void* d_out, int out_size)
{
    (void)in_sizes; (void)n_in; (void)out_size;
    const float* x       = (const float*)d_in[0];
    const float* enc     = (const float*)d_in[1];
    const unsigned int* mask = (const unsigned int*)d_in[2];
    const float* gamma   = (const float*)d_in[3];
    const float* beta    = (const float*)d_in[4];
    const float* qkv_w   = (const float*)d_in[5];
    const float* qkv_b   = (const float*)d_in[6];
    const float* ekv_w   = (const float*)d_in[7];
    const float* ekv_b   = (const float*)d_in[8];
    const float* proj_w  = (const float*)d_in[9];
    const float* proj_b  = (const float*)d_in[10];
    float* out = (float*)d_out;

    float *nrm, *att;
    cudaGetSymbolAddress((void**)&nrm, g_nrm);
    cudaGetSymbolAddress((void**)&att, g_att);

    // 1. GroupNorm
    gn_kernel<<<B_ * GROUPS_, 256>>>(x, gamma, beta, nrm);

    // 2. qkv projection -> bf16 packs (q scaled 1/8)
    gemm_tc<<<dim3(8, 12, B_), 256>>>(qkv_w, nrm, qkv_b, nullptr, nullptr,
        1536, 1024, 512, T_, (long long)C_ * T_, 0, 0, 1);

    // 3. encoder kv -> bf16 packs at cols 1024+
    gemm_tc<<<dim3(1, 8, B_), 256>>>(ekv_w, enc, ekv_b, nullptr, nullptr,
        1024, S_, 512, S_, (long long)C_ * S_, 0, 0, 2);

    // 4. bf16 flash attention: 64 bh x 8 q-tiles of 128
    cudaFuncSetAttribute(attn_bf16_kernel, cudaFuncAttributeMaxDynamicSharedMemorySize, ATT_SMEM);
    attn_bf16_kernel<<<dim3(8, 64), 256, ATT_SMEM>>>(mask);

    // 5. output projection + bias + residual -> d_out
    gemm_tc<<<dim3(8, 4, B_), 256>>>(proj_w, att, proj_b, x, out,
        512, 1024, 512, T_, (long long)C_ * T_, T_, (long long)C_ * T_, 0);
}

// round 7
// speedup vs baseline: 7.9190x; 2.1876x over previous
#include <cuda_runtime.h>
#include <cuda_bf16.h>
#include <cstdint>

#define B_      8
#define C_      512
#define T_      1024
#define HEADS_  8
#define CH_     64
#define S_      77
#define L_      1101
#define LP_     1152
#define GROUPS_ 32
#define CPG_    16

// Scratch (static device globals)
static __device__ __nv_bfloat16 g_nrmb[B_ * C_ * T_];           // GN output bf16 [b][c][t]
static __device__ __nv_bfloat16 g_attb[B_ * C_ * T_];           // attn output bf16 [b][c][t]
static __device__ __nv_bfloat16 g_qp[B_ * HEADS_ * CH_ * T_];   // [bh][ch][t], pre-scaled 1/8
static __device__ __nv_bfloat16 g_kp[B_ * HEADS_ * CH_ * LP_];  // [bh][ch][self|enc|pad]
static __device__ __nv_bfloat16 g_vp[B_ * HEADS_ * CH_ * LP_];
static __device__ __nv_bfloat16 g_qkvwb[1536 * 512];
static __device__ __nv_bfloat16 g_ekvwb[1024 * 512];
static __device__ __nv_bfloat16 g_projwb[512 * 512];
static __device__ __nv_bfloat16 g_encb[B_ * 512 * 128];         // padded 77->128, zero-filled

// ---------------------------------------------------------------------------
// PTX helpers
// ---------------------------------------------------------------------------
__device__ __forceinline__ uint32_t smem_u32(const void* p) {
    uint32_t a;
    asm("{ .reg .u64 t; cvta.to.shared.u64 t, %1; cvt.u32.u64 %0, t; }" : "=r"(a) : "l"(p));
    return a;
}
__device__ __forceinline__ void mma_bf16(float* c, const uint32_t* a, const uint32_t* b) {
    asm volatile("mma.sync.aligned.m16n8k16.row.col.f32.bf16.bf16.f32 "
        "{%0,%1,%2,%3}, {%4,%5,%6,%7}, {%8,%9}, {%0,%1,%2,%3};"
        : "+f"(c[0]), "+f"(c[1]), "+f"(c[2]), "+f"(c[3])
        : "r"(a[0]), "r"(a[1]), "r"(a[2]), "r"(a[3]), "r"(b[0]), "r"(b[1]));
}
__device__ __forceinline__ void ldsm4(uint32_t* r, uint32_t a) {
    asm volatile("ldmatrix.sync.aligned.m8n8.x4.shared.b16 {%0,%1,%2,%3}, [%4];"
        : "=r"(r[0]), "=r"(r[1]), "=r"(r[2]), "=r"(r[3]) : "r"(a));
}
__device__ __forceinline__ void ldsm4t(uint32_t* r, uint32_t a) {
    asm volatile("ldmatrix.sync.aligned.m8n8.x4.trans.shared.b16 {%0,%1,%2,%3}, [%4];"
        : "=r"(r[0]), "=r"(r[1]), "=r"(r[2]), "=r"(r[3]) : "r"(a));
}
__device__ __forceinline__ void cp16(uint32_t dst, const void* src) {
    asm volatile("cp.async.cg.shared.global [%0], [%1], 16;" :: "r"(dst), "l"(src));
}
#define CP_COMMIT() asm volatile("cp.async.commit_group;" ::: "memory")
#define CP_WAIT1()  asm volatile("cp.async.wait_group 1;" ::: "memory")

__device__ __forceinline__ __nv_bfloat162 pack2(float a, float b) {
    __nv_bfloat162 w;
    w.x = __float2bfloat16_rn(a);
    w.y = __float2bfloat16_rn(b);
    return w;
}

// ---------------------------------------------------------------------------
// Pre-convert weights + encoder to bf16 (encoder padded to 128 cols)
// ---------------------------------------------------------------------------
#define NQW 786432
#define NEW 524288
#define NPW 262144
#define NEN 524288
__global__ __launch_bounds__(256) void conv_kernel(
    const float* __restrict__ qkvw, const float* __restrict__ ekvw,
    const float* __restrict__ projw, const float* __restrict__ enc)
{
    int i = blockIdx.x * 256 + threadIdx.x;
    if (i < NQW) g_qkvwb[i] = __float2bfloat16_rn(qkvw[i]);
    else if (i < NQW + NEW) g_ekvwb[i - NQW] = __float2bfloat16_rn(ekvw[i - NQW]);
    else if (i < NQW + NEW + NPW) g_projwb[i - NQW - NEW] = __float2bfloat16_rn(projw[i - NQW - NEW]);
    else {
        int e = i - NQW - NEW - NPW;
        int t = e & 127, row = e >> 7;   // row = b*512 + c
        g_encb[e] = (t < S_) ? __float2bfloat16_rn(enc[row * S_ + t]) : __nv_bfloat16(0.f);
    }
}

// ---------------------------------------------------------------------------
// GroupNorm32 -> bf16
// ---------------------------------------------------------------------------
__global__ __launch_bounds__(256) void gn_kernel(
    const float* __restrict__ x, const float* __restrict__ gamma,
    const float* __restrict__ beta)
{
    int b = blockIdx.x / GROUPS_, g = blockIdx.x % GROUPS_;
    const float* xp = x + ((size_t)b * C_ + g * CPG_) * T_;
    __nv_bfloat16* op = g_nrmb + ((size_t)b * C_ + g * CPG_) * T_;
    const int N = CPG_ * T_;

    float s = 0.f, q = 0.f;
    for (int i = threadIdx.x; i < N; i += 256) {
        float v = xp[i];
        s += v; q = fmaf(v, v, q);
    }
    __shared__ float rs[256], rq[256];
    rs[threadIdx.x] = s; rq[threadIdx.x] = q;
    __syncthreads();
    for (int o = 128; o > 0; o >>= 1) {
        if (threadIdx.x < o) { rs[threadIdx.x] += rs[threadIdx.x + o]; rq[threadIdx.x] += rq[threadIdx.x + o]; }
        __syncthreads();
    }
    float mean = rs[0] * (1.f / N);
    float var  = rq[0] * (1.f / N) - mean * mean;
    float inv  = rsqrtf(var + 1e-5f);
    for (int i = threadIdx.x; i < N; i += 256) {
        int c = g * CPG_ + (i >> 10);
        op[i] = __float2bfloat16_rn((xp[i] - mean) * inv * gamma[c] + beta[c]);
    }
}

// ---------------------------------------------------------------------------
// Epilogue pack writer (head-major row decode, verified round 6)
// ---------------------------------------------------------------------------
__device__ __forceinline__ void write_pack(int mode, int z, int m, int n, float v0, float v1, int N) {
    int h, type, ch;
    if (mode == 1) {
        h = m / 192;
        int sub = m - h * 192;
        type = sub >> 6; ch = sub & 63;
    } else {
        h = m >> 7;
        type = (m >> 6) & 1; ch = m & 63;
    }
    size_t row = (size_t)(z * 8 + h) * 64 + ch;
    if (mode == 1) {
        if (type == 0) {
            *(__nv_bfloat162*)&g_qp[row * T_ + n] = pack2(v0 * 0.125f, v1 * 0.125f);
        } else {
            __nv_bfloat16* p = (type == 1 ? g_kp : g_vp) + row * LP_ + n;
            *(__nv_bfloat162*)p = pack2(v0, v1);
        }
    } else {
        __nv_bfloat16* p = (type == 0 ? g_kp : g_vp) + row * LP_ + 1024 + n;
        if (n + 1 < N)      *(__nv_bfloat162*)p = pack2(v0, v1);
        else if (n < N)     *p = __float2bfloat16_rn(v0);
    }
}

// ---------------------------------------------------------------------------
// bf16 mma.sync GEMM, cp.async double-buffered, ldmatrix fragments.
// C[z][m][n] = A[m][:] . B[z][:][n] + bias[m] (+res).  Tile 128x128, Kstep 32.
// A bf16 [M][K] row-major; B bf16 [z][K][ldb] (n-contiguous, padded loads ok).
// smem: As [m128][k32] 64B rows; Bs [k32][n128] 256B rows; both XOR-swizzled.
// ---------------------------------------------------------------------------
__global__ __launch_bounds__(256, 2) void gemm_bf(
    const __nv_bfloat16* __restrict__ A, const __nv_bfloat16* __restrict__ Bm,
    const float* __restrict__ bias, const float* __restrict__ res,
    float* __restrict__ Cm, int M, int N, int K,
    int ldb, long long sB, int ldc, long long sC, int mode)
{
    __shared__ __nv_bfloat16 As[2][4096];   // 2 x 8KB
    __shared__ __nv_bfloat16 Bs[2][4096];   // 2 x 8KB
    const uint32_t sa = smem_u32(As), sb = smem_u32(Bs);

    int bm = blockIdx.y << 7, bn = blockIdx.x << 7;
    int tid = threadIdx.x, wid = tid >> 5, lane = tid & 31;
    int wm = (wid >> 2) << 6, wn = (wid & 3) << 5;
    int gr = lane >> 2, gc = lane & 3;

    const __nv_bfloat16* Ab = A + (size_t)bm * K;
    const __nv_bfloat16* Bb = Bm + (size_t)blockIdx.z * sB + bn;

    // ldsm addressing precompute
    int a_m  = (lane & 7) + (((lane >> 3) & 1) << 3);   // row offset within 16
    int a_kc = lane >> 4;                               // k-chunk half (0/1)
    int b_kr = (lane & 7) + (((lane >> 3) & 1) << 3);   // k row offset within 16
    int b_sg = (wid & 3) * 4 + (lane >> 4);             // n-chunk base for this warp

    float c[4][4][4];
#pragma unroll
    for (int i = 0; i < 4; i++)
#pragma unroll
        for (int j = 0; j < 4; j++)
#pragma unroll
            for (int l = 0; l < 4; l++) c[i][j][l] = 0.f;

    // async tile loaders (4 cp16 per thread per K-step)
    auto load_tiles = [&](int k0, int buf) {
#pragma unroll
        for (int j = 0; j < 2; j++) {
            int idx = tid + (j << 8);
            int m = idx >> 2, kc = idx & 3;
            cp16(sa + (buf << 13) + m * 64 + ((kc ^ ((m >> 1) & 3)) << 4),
                 Ab + (size_t)m * K + k0 + kc * 8);
        }
#pragma unroll
        for (int j = 0; j < 2; j++) {
            int idx = tid + (j << 8);
            int k = idx >> 4, seg = idx & 15;
            cp16(sb + (buf << 13) + k * 256 + ((seg ^ (k & 7)) << 4),
                 Bb + (size_t)(k0 + k) * ldb + seg * 8);
        }
    };

    int nsteps = K >> 5;   // K=512 -> 16
    load_tiles(0, 0); CP_COMMIT();
    load_tiles(32, 1); CP_COMMIT();

    for (int s = 0; s < nsteps; s++) {
        CP_WAIT1();
        __syncthreads();
        int buf = s & 1;
        uint32_t ab = sa + (buf << 13), bb = sb + (buf << 13);

#pragma unroll
        for (int kt = 0; kt < 2; kt++) {
            uint32_t af[4][4];
            int kc = (kt << 1) + a_kc;
#pragma unroll
            for (int mt = 0; mt < 4; mt++) {
                int m = wm + (mt << 4) + a_m;
                ldsm4(af[mt], ab + m * 64 + ((kc ^ ((m >> 1) & 3)) << 4));
            }
            uint32_t bf[4][2];
            int kr = (kt << 4) + b_kr;
#pragma unroll
            for (int np = 0; np < 2; np++) {
                uint32_t t4[4];
                int seg = b_sg + (np << 1);
                ldsm4t(t4, bb + kr * 256 + ((seg ^ (kr & 7)) << 4));
                bf[np * 2][0] = t4[0]; bf[np * 2][1] = t4[1];
                bf[np * 2 + 1][0] = t4[2]; bf[np * 2 + 1][1] = t4[3];
            }
#pragma unroll
            for (int mt = 0; mt < 4; mt++)
#pragma unroll
                for (int nf = 0; nf < 4; nf++)
                    mma_bf16(c[mt][nf], af[mt], bf[nf]);
        }
        __syncthreads();
        if (s + 2 < nsteps) { load_tiles((s + 2) << 5, buf); }
        CP_COMMIT();
    }

    float* Cp = Cm ? (Cm + (size_t)blockIdx.z * sC) : nullptr;
    const float* Rp = res ? (res + (size_t)blockIdx.z * sC) : nullptr;

#pragma unroll
    for (int mt = 0; mt < 4; mt++) {
        int m0 = bm + wm + (mt << 4) + gr;
        float bv0 = bias[m0], bv1 = bias[m0 + 8];
#pragma unroll
        for (int nt = 0; nt < 4; nt++) {
            int n = bn + wn + (nt << 3) + (gc << 1);
            float v0 = c[mt][nt][0] + bv0, v1 = c[mt][nt][1] + bv0;
            float v2 = c[mt][nt][2] + bv1, v3 = c[mt][nt][3] + bv1;
            if (mode == 0) {
                float a0 = v0, a1 = v1, a2 = v2, a3 = v3;
                if (Rp) {
                    a0 += Rp[(size_t)m0 * ldc + n];       a1 += Rp[(size_t)m0 * ldc + n + 1];
                    a2 += Rp[(size_t)(m0 + 8) * ldc + n]; a3 += Rp[(size_t)(m0 + 8) * ldc + n + 1];
                }
                Cp[(size_t)m0 * ldc + n] = a0;       Cp[(size_t)m0 * ldc + n + 1] = a1;
                Cp[(size_t)(m0 + 8) * ldc + n] = a2; Cp[(size_t)(m0 + 8) * ldc + n + 1] = a3;
            } else {
                write_pack(mode, blockIdx.z, m0, n, v0, v1, N);
                write_pack(mode, blockIdx.z, m0 + 8, n, v2, v3, N);
            }
        }
    }
}

// ---------------------------------------------------------------------------
// bf16 mma.sync flash attention (unchanged core; epilogue now writes bf16)
// ---------------------------------------------------------------------------
#define QS_OFF   0
#define KS_OFF   16384
#define VS_OFF   32768
#define PS_OFF   49152
#define MADD_OFF 65536
#define ATT_SMEM 70144

__device__ __forceinline__ void prefetch_kv(uint32_t sbase,
    const __nv_bfloat16* Kg, const __nv_bfloat16* Vg, int c, int buf, int tid)
{
#pragma unroll
    for (int j = 0; j < 4; j++) {
        int i = tid + (j << 8);
        int sel = i >> 9, ch = (i >> 3) & 63, seg = i & 7;
        const __nv_bfloat16* src = (sel ? Vg : Kg) + ch * LP_ + (c << 6) + (seg << 3);
        uint32_t dst = sbase + (sel ? VS_OFF : KS_OFF) + (buf << 13)
                     + (ch << 7) + ((seg ^ (ch & 7)) << 4);
        cp16(dst, src);
    }
}

__global__ __launch_bounds__(256, 2) void attn_bf16_kernel(const unsigned int* __restrict__ mask)
{
    extern __shared__ char smc[];
    const uint32_t sbase = smem_u32(smc);
    int tid = threadIdx.x, lane = tid & 31, wid = tid >> 5;
    int gr = lane >> 2, gc = lane & 3, l7 = lane & 7, g = lane >> 3;
    int bh = blockIdx.y, h = bh & 7;
    int t0 = blockIdx.x << 7;
    int r0w = wid << 4;

    const __nv_bfloat16* Qg = g_qp + (size_t)bh * 64 * T_;
    const __nv_bfloat16* Kg = g_kp + (size_t)bh * 64 * LP_;
    const __nv_bfloat16* Vg = g_vp + (size_t)bh * 64 * LP_;

    float* madd = (float*)(smc + MADD_OFF);
    for (int s = tid; s < LP_; s += 256)
        madd[s] = (s < 1024) ? 0.f
                : (s < L_ ? (mask[h * S_ + (s - 1024)] ? 0.f : -10000.f) : -1e30f);

    for (int i = tid; i < 1024; i += 256) {
        int ch = i >> 4, seg = i & 15;
        uint4 v = *(const uint4*)(Qg + ch * T_ + t0 + seg * 8);
        *(uint4*)(smc + QS_OFF + ch * 256 + ((seg ^ (ch & 7)) << 4)) = v;
    }
    __syncthreads();

    uint32_t qf[4][4];
#pragma unroll
    for (int kt = 0; kt < 4; kt++) {
        int ch = kt * 16 + l7 + ((g >> 1) << 3);
        int tb = (r0w << 1) + ((g & 1) << 4);
        ldsm4t(qf[kt], sbase + QS_OFF + ch * 256 + (tb ^ ((ch & 7) << 4)));
    }

    float o[8][4];
#pragma unroll
    for (int nt = 0; nt < 8; nt++)
#pragma unroll
        for (int l = 0; l < 4; l++) o[nt][l] = 0.f;
    float lsum0 = 0.f, lsum1 = 0.f;

    prefetch_kv(sbase, Kg, Vg, 0, 0, tid); CP_COMMIT();
    prefetch_kv(sbase, Kg, Vg, 1, 1, tid); CP_COMMIT();

    for (int c = 0; c < 18; c++) {
        CP_WAIT1();
        __syncthreads();
        int buf = c & 1;
        uint32_t kb = sbase + KS_OFF + (buf << 13);
        uint32_t vb = sbase + VS_OFF + (buf << 13);

        float s8[8][4];
#pragma unroll
        for (int nt = 0; nt < 8; nt++)
#pragma unroll
            for (int l = 0; l < 4; l++) s8[nt][l] = 0.f;
#pragma unroll
        for (int kt = 0; kt < 4; kt++) {
            int ch = kt * 16 + l7 + ((g & 1) << 3);
#pragma unroll
            for (int ntp = 0; ntp < 4; ntp++) {
                uint32_t bf4[4];
                int seg = ntp * 2 + (g >> 1);
                ldsm4t(bf4, kb + (ch << 7) + ((seg ^ (ch & 7)) << 4));
                mma_bf16(s8[ntp * 2],     qf[kt], bf4);
                mma_bf16(s8[ntp * 2 + 1], qf[kt], bf4 + 2);
            }
        }

        int colb = c << 6;
#pragma unroll
        for (int nt = 0; nt < 8; nt++) {
            int col = colb + nt * 8 + gc * 2;
            float m0 = madd[col], m1 = madd[col + 1];
            float p0 = __expf(s8[nt][0] + m0), p1 = __expf(s8[nt][1] + m1);
            float p2 = __expf(s8[nt][2] + m0), p3 = __expf(s8[nt][3] + m1);
            lsum0 += p0 + p1; lsum1 += p2 + p3;
            int row0 = r0w + gr, row1 = row0 + 8;
            *(__nv_bfloat162*)(smc + PS_OFF + row0 * 128 + ((nt ^ (row0 & 7)) << 4) + gc * 4) = pack2(p0, p1);
            *(__nv_bfloat162*)(smc + PS_OFF + row1 * 128 + ((nt ^ (row1 & 7)) << 4) + gc * 4) = pack2(p2, p3);
        }
        __syncwarp();

#pragma unroll
        for (int kt = 0; kt < 4; kt++) {
            uint32_t af[4];
            int row = r0w + l7 + ((g & 1) << 3);
            int pseg = kt * 2 + (g >> 1);
            ldsm4(af, sbase + PS_OFF + (row << 7) + ((pseg ^ (row & 7)) << 4));
#pragma unroll
            for (int ntp = 0; ntp < 4; ntp++) {
                uint32_t bv4[4];
                int ch = (ntp * 2 + (g >> 1)) * 8 + l7;
                int sseg = kt * 2 + (g & 1);
                ldsm4(bv4, vb + (ch << 7) + ((sseg ^ (ch & 7)) << 4));
                mma_bf16(o[ntp * 2],     af, bv4);
                mma_bf16(o[ntp * 2 + 1], af, bv4 + 2);
            }
        }
        __syncthreads();
        if (c + 2 < 18) prefetch_kv(sbase, Kg, Vg, c + 2, buf, tid);
        CP_COMMIT();
    }

    lsum0 += __shfl_xor_sync(0xffffffffu, lsum0, 1);
    lsum0 += __shfl_xor_sync(0xffffffffu, lsum0, 2);
    lsum1 += __shfl_xor_sync(0xffffffffu, lsum1, 1);
    lsum1 += __shfl_xor_sync(0xffffffffu, lsum1, 2);
    float inv0 = 1.f / lsum0, inv1 = 1.f / lsum1;

    float* tr = (float*)smc;   // [64][132] floats
    int r0g = r0w + gr;
#pragma unroll
    for (int nt = 0; nt < 8; nt++) {
        int ch = nt * 8 + gc * 2;
        tr[ch * 132 + r0g]           = o[nt][0] * inv0;
        tr[(ch + 1) * 132 + r0g]     = o[nt][1] * inv0;
        tr[ch * 132 + r0g + 8]       = o[nt][2] * inv1;
        tr[(ch + 1) * 132 + r0g + 8] = o[nt][3] * inv1;
    }
    __syncthreads();
    __nv_bfloat16* ob = g_attb + ((size_t)(bh >> 3) * C_ + h * CH_) * T_ + t0;
    for (int i = tid; i < 8192; i += 256) {
        int ch = i >> 7, t = i & 127;
        ob[(size_t)ch * T_ + t] = __float2bfloat16_rn(tr[ch * 132 + t]);
    }
}

// ---------------------------------------------------------------------------
extern "C" void kernel_launch(void* const* d_in, const int* in_sizes, int n_in,
                              void* d_out, int out_size)
{
    (void)in_sizes; (void)n_in; (void)out_size;
    const float* x       = (const float*)d_in[0];
    const float* enc     = (const float*)d_in[1];
    const unsigned int* mask = (const unsigned int*)d_in[2];
    const float* gamma   = (const float*)d_in[3];
    const float* beta    = (const float*)d_in[4];
    const float* qkv_w   = (const float*)d_in[5];
    const float* qkv_b   = (const float*)d_in[6];
    const float* ekv_w   = (const float*)d_in[7];
    const float* ekv_b   = (const float*)d_in[8];
    const float* proj_w  = (const float*)d_in[9];
    const float* proj_b  = (const float*)d_in[10];
    float* out = (float*)d_out;

    __nv_bfloat16 *qkvwb, *ekvwb, *projwb, *encb, *nrmb, *attb;
    cudaGetSymbolAddress((void**)&qkvwb, g_qkvwb);
    cudaGetSymbolAddress((void**)&ekvwb, g_ekvwb);
    cudaGetSymbolAddress((void**)&projwb, g_projwb);
    cudaGetSymbolAddress((void**)&encb, g_encb);
    cudaGetSymbolAddress((void**)&nrmb, g_nrmb);
    cudaGetSymbolAddress((void**)&attb, g_attb);

    // 0. pre-convert weights + encoder to bf16
    conv_kernel<<<(NQW + NEW + NPW + NEN) / 256, 256>>>(qkv_w, ekv_w, proj_w, enc);

    // 1. GroupNorm -> bf16
    gn_kernel<<<B_ * GROUPS_, 256>>>(x, gamma, beta);

    // 2. qkv projection -> bf16 q/k/v packs
    gemm_bf<<<dim3(8, 12, B_), 256>>>(qkvwb, nrmb, qkv_b, nullptr, nullptr,
        1536, 1024, 512, T_, (long long)C_ * T_, 0, 0, 1);

    // 3. encoder kv -> packs at cols 1024+ (B padded to 128)
    gemm_bf<<<dim3(1, 8, B_), 256>>>(ekvwb, encb, ekv_b, nullptr, nullptr,
        1024, S_, 512, 128, (long long)C_ * 128, 0, 0, 2);

    // 4. bf16 flash attention
    cudaFuncSetAttribute(attn_bf16_kernel, cudaFuncAttributeMaxDynamicSharedMemorySize, ATT_SMEM);
    attn_bf16_kernel<<<dim3(8, 64), 256, ATT_SMEM>>>(mask);

    // 5. output projection + bias + residual -> d_out
    gemm_bf<<<dim3(8, 4, B_), 256>>>(projwb, attb, proj_b, x, out,
        512, 1024, 512, T_, (long long)C_ * T_, T_, (long long)C_ * T_, 0);
}

// round 8
// speedup vs baseline: 8.5049x; 1.0740x over previous
#include <cuda_runtime.h>
#include <cuda_bf16.h>
#include <cstdint>

#define B_      8
#define C_      512
#define T_      1024
#define HEADS_  8
#define CH_     64
#define S_      77
#define L_      1101
#define LP_     1152
#define GROUPS_ 32
#define CPG_    16

// Scratch (static device globals)
static __device__ __nv_bfloat16 g_nrmb[B_ * C_ * T_];
static __device__ __nv_bfloat16 g_attb[B_ * C_ * T_];
static __device__ __nv_bfloat16 g_qp[B_ * HEADS_ * CH_ * T_];   // [bh][ch][t], pre-scaled 1/8
static __device__ __nv_bfloat16 g_kp[B_ * HEADS_ * CH_ * LP_];  // [bh][ch][self|enc|pad]
static __device__ __nv_bfloat16 g_vp[B_ * HEADS_ * CH_ * LP_];
static __device__ __nv_bfloat16 g_qkvwb[1536 * 512];
static __device__ __nv_bfloat16 g_ekvwb[1024 * 512];
static __device__ __nv_bfloat16 g_projwb[512 * 512];
static __device__ __nv_bfloat16 g_encb[B_ * 512 * 128];

// ---------------------------------------------------------------------------
// PTX helpers
// ---------------------------------------------------------------------------
__device__ __forceinline__ uint32_t smem_u32(const void* p) {
    uint32_t a;
    asm("{ .reg .u64 t; cvta.to.shared.u64 t, %1; cvt.u32.u64 %0, t; }" : "=r"(a) : "l"(p));
    return a;
}
__device__ __forceinline__ void mma_bf16(float* c, const uint32_t* a, const uint32_t* b) {
    asm volatile("mma.sync.aligned.m16n8k16.row.col.f32.bf16.bf16.f32 "
        "{%0,%1,%2,%3}, {%4,%5,%6,%7}, {%8,%9}, {%0,%1,%2,%3};"
        : "+f"(c[0]), "+f"(c[1]), "+f"(c[2]), "+f"(c[3])
        : "r"(a[0]), "r"(a[1]), "r"(a[2]), "r"(a[3]), "r"(b[0]), "r"(b[1]));
}
__device__ __forceinline__ void ldsm4(uint32_t* r, uint32_t a) {
    asm volatile("ldmatrix.sync.aligned.m8n8.x4.shared.b16 {%0,%1,%2,%3}, [%4];"
        : "=r"(r[0]), "=r"(r[1]), "=r"(r[2]), "=r"(r[3]) : "r"(a));
}
__device__ __forceinline__ void ldsm4t(uint32_t* r, uint32_t a) {
    asm volatile("ldmatrix.sync.aligned.m8n8.x4.trans.shared.b16 {%0,%1,%2,%3}, [%4];"
        : "=r"(r[0]), "=r"(r[1]), "=r"(r[2]), "=r"(r[3]) : "r"(a));
}
__device__ __forceinline__ void cp16(uint32_t dst, const void* src) {
    asm volatile("cp.async.cg.shared.global [%0], [%1], 16;" :: "r"(dst), "l"(src));
}
#define CP_COMMIT() asm volatile("cp.async.commit_group;" ::: "memory")
#define CP_WAIT1()  asm volatile("cp.async.wait_group 1;" ::: "memory")

__device__ __forceinline__ __nv_bfloat162 pack2(float a, float b) {
    __nv_bfloat162 w;
    w.x = __float2bfloat16_rn(a);
    w.y = __float2bfloat16_rn(b);
    return w;
}
__device__ __forceinline__ uint32_t pku(float lo, float hi) {
    __nv_bfloat162 t = pack2(lo, hi);
    return *reinterpret_cast<uint32_t*>(&t);
}

// ---------------------------------------------------------------------------
// Pre-convert weights + encoder to bf16 (encoder padded to 128 cols)
// ---------------------------------------------------------------------------
#define NQW 786432
#define NEW 524288
#define NPW 262144
#define NEN 524288
__global__ __launch_bounds__(256) void conv_kernel(
    const float* __restrict__ qkvw, const float* __restrict__ ekvw,
    const float* __restrict__ projw, const float* __restrict__ enc)
{
    int i = blockIdx.x * 256 + threadIdx.x;
    if (i < NQW) g_qkvwb[i] = __float2bfloat16_rn(qkvw[i]);
    else if (i < NQW + NEW) g_ekvwb[i - NQW] = __float2bfloat16_rn(ekvw[i - NQW]);
    else if (i < NQW + NEW + NPW) g_projwb[i - NQW - NEW] = __float2bfloat16_rn(projw[i - NQW - NEW]);
    else {
        int e = i - NQW - NEW - NPW;
        int t = e & 127, row = e >> 7;
        g_encb[e] = (t < S_) ? __float2bfloat16_rn(enc[row * S_ + t]) : __nv_bfloat16(0.f);
    }
}

// ---------------------------------------------------------------------------
// GroupNorm32 -> bf16
// ---------------------------------------------------------------------------
__global__ __launch_bounds__(256) void gn_kernel(
    const float* __restrict__ x, const float* __restrict__ gamma,
    const float* __restrict__ beta)
{
    int b = blockIdx.x / GROUPS_, g = blockIdx.x % GROUPS_;
    const float* xp = x + ((size_t)b * C_ + g * CPG_) * T_;
    __nv_bfloat16* op = g_nrmb + ((size_t)b * C_ + g * CPG_) * T_;
    const int N = CPG_ * T_;

    float s = 0.f, q = 0.f;
    for (int i = threadIdx.x; i < N; i += 256) {
        float v = xp[i];
        s += v; q = fmaf(v, v, q);
    }
    __shared__ float rs[256], rq[256];
    rs[threadIdx.x] = s; rq[threadIdx.x] = q;
    __syncthreads();
    for (int o = 128; o > 0; o >>= 1) {
        if (threadIdx.x < o) { rs[threadIdx.x] += rs[threadIdx.x + o]; rq[threadIdx.x] += rq[threadIdx.x + o]; }
        __syncthreads();
    }
    float mean = rs[0] * (1.f / N);
    float var  = rq[0] * (1.f / N) - mean * mean;
    float inv  = rsqrtf(var + 1e-5f);
    for (int i = threadIdx.x; i < N; i += 256) {
        int c = g * CPG_ + (i >> 10);
        op[i] = __float2bfloat16_rn((xp[i] - mean) * inv * gamma[c] + beta[c]);
    }
}

// ---------------------------------------------------------------------------
// Epilogue pack writer (head-major row decode)
// ---------------------------------------------------------------------------
__device__ __forceinline__ void write_pack(int mode, int z, int m, int n, float v0, float v1, int N) {
    int h, type, ch;
    if (mode == 1) {
        h = m / 192;
        int sub = m - h * 192;
        type = sub >> 6; ch = sub & 63;
    } else {
        h = m >> 7;
        type = (m >> 6) & 1; ch = m & 63;
    }
    size_t row = (size_t)(z * 8 + h) * 64 + ch;
    if (mode == 1) {
        if (type == 0) {
            *(__nv_bfloat162*)&g_qp[row * T_ + n] = pack2(v0 * 0.125f, v1 * 0.125f);
        } else {
            __nv_bfloat16* p = (type == 1 ? g_kp : g_vp) + row * LP_ + n;
            *(__nv_bfloat162*)p = pack2(v0, v1);
        }
    } else {
        __nv_bfloat16* p = (type == 0 ? g_kp : g_vp) + row * LP_ + 1024 + n;
        if (n + 1 < N)      *(__nv_bfloat162*)p = pack2(v0, v1);
        else if (n < N)     *p = __float2bfloat16_rn(v0);
    }
}

// ---------------------------------------------------------------------------
// bf16 mma.sync GEMM, 3-stage cp.async ring (one syncthreads per K-step).
// ---------------------------------------------------------------------------
__global__ __launch_bounds__(256, 2) void gemm_bf(
    const __nv_bfloat16* __restrict__ A, const __nv_bfloat16* __restrict__ Bm,
    const float* __restrict__ bias, const float* __restrict__ res,
    float* __restrict__ Cm, int M, int N, int K,
    int ldb, long long sB, int ldc, long long sC, int mode)
{
    __shared__ __nv_bfloat16 As[3][4096];   // 3 x 8KB
    __shared__ __nv_bfloat16 Bs[3][4096];
    const uint32_t sa = smem_u32(As), sb = smem_u32(Bs);

    int bm = blockIdx.y << 7, bn = blockIdx.x << 7;
    int tid = threadIdx.x, wid = tid >> 5, lane = tid & 31;
    int wm = (wid >> 2) << 6, wn = (wid & 3) << 5;
    int gr = lane >> 2, gc = lane & 3;

    const __nv_bfloat16* Ab = A + (size_t)bm * K;
    const __nv_bfloat16* Bb = Bm + (size_t)blockIdx.z * sB + bn;

    int a_m  = (lane & 7) + (((lane >> 3) & 1) << 3);
    int a_kc = lane >> 4;
    int b_kr = (lane & 7) + (((lane >> 3) & 1) << 3);
    int b_sg = (wid & 3) * 4 + (lane >> 4);

    float c[4][4][4];
#pragma unroll
    for (int i = 0; i < 4; i++)
#pragma unroll
        for (int j = 0; j < 4; j++)
#pragma unroll
            for (int l = 0; l < 4; l++) c[i][j][l] = 0.f;

    auto load_tiles = [&](int k0, int slot) {
#pragma unroll
        for (int j = 0; j < 2; j++) {
            int idx = tid + (j << 8);
            int m = idx >> 2, kc = idx & 3;
            cp16(sa + slot * 8192 + m * 64 + ((kc ^ ((m >> 1) & 3)) << 4),
                 Ab + (size_t)m * K + k0 + kc * 8);
        }
#pragma unroll
        for (int j = 0; j < 2; j++) {
            int idx = tid + (j << 8);
            int k = idx >> 4, seg = idx & 15;
            cp16(sb + slot * 8192 + k * 256 + ((seg ^ (k & 7)) << 4),
                 Bb + (size_t)(k0 + k) * ldb + seg * 8);
        }
    };

    int nsteps = K >> 5;
    load_tiles(0, 0); CP_COMMIT();
    load_tiles(32, 1); CP_COMMIT();

    int sl0 = 0, sl2 = 2;
    for (int s = 0; s < nsteps; s++) {
        CP_WAIT1();
        __syncthreads();
        if (s + 2 < nsteps) load_tiles((s + 2) << 5, sl2);
        CP_COMMIT();
        uint32_t ab = sa + sl0 * 8192, bb = sb + sl0 * 8192;

#pragma unroll
        for (int kt = 0; kt < 2; kt++) {
            uint32_t af[4][4];
            int kc = (kt << 1) + a_kc;
#pragma unroll
            for (int mt = 0; mt < 4; mt++) {
                int m = wm + (mt << 4) + a_m;
                ldsm4(af[mt], ab + m * 64 + ((kc ^ ((m >> 1) & 3)) << 4));
            }
            uint32_t bf[4][2];
            int kr = (kt << 4) + b_kr;
#pragma unroll
            for (int np = 0; np < 2; np++) {
                uint32_t t4[4];
                int seg = b_sg + (np << 1);
                ldsm4t(t4, bb + kr * 256 + ((seg ^ (kr & 7)) << 4));
                bf[np * 2][0] = t4[0]; bf[np * 2][1] = t4[1];
                bf[np * 2 + 1][0] = t4[2]; bf[np * 2 + 1][1] = t4[3];
            }
#pragma unroll
            for (int mt = 0; mt < 4; mt++)
#pragma unroll
                for (int nf = 0; nf < 4; nf++)
                    mma_bf16(c[mt][nf], af[mt], bf[nf]);
        }
        sl0 = (sl0 == 2) ? 0 : sl0 + 1;
        sl2 = (sl2 == 2) ? 0 : sl2 + 1;
    }

    float* Cp = Cm ? (Cm + (size_t)blockIdx.z * sC) : nullptr;
    const float* Rp = res ? (res + (size_t)blockIdx.z * sC) : nullptr;

#pragma unroll
    for (int mt = 0; mt < 4; mt++) {
        int m0 = bm + wm + (mt << 4) + gr;
        float bv0 = bias[m0], bv1 = bias[m0 + 8];
#pragma unroll
        for (int nt = 0; nt < 4; nt++) {
            int n = bn + wn + (nt << 3) + (gc << 1);
            float v0 = c[mt][nt][0] + bv0, v1 = c[mt][nt][1] + bv0;
            float v2 = c[mt][nt][2] + bv1, v3 = c[mt][nt][3] + bv1;
            if (mode == 0) {
                float a0 = v0, a1 = v1, a2 = v2, a3 = v3;
                if (Rp) {
                    a0 += Rp[(size_t)m0 * ldc + n];       a1 += Rp[(size_t)m0 * ldc + n + 1];
                    a2 += Rp[(size_t)(m0 + 8) * ldc + n]; a3 += Rp[(size_t)(m0 + 8) * ldc + n + 1];
                }
                Cp[(size_t)m0 * ldc + n] = a0;       Cp[(size_t)m0 * ldc + n + 1] = a1;
                Cp[(size_t)(m0 + 8) * ldc + n] = a2; Cp[(size_t)(m0 + 8) * ldc + n + 1] = a3;
            } else {
                write_pack(mode, blockIdx.z, m0, n, v0, v1, N);
                write_pack(mode, blockIdx.z, m0 + 8, n, v2, v3, N);
            }
        }
    }
}

// ---------------------------------------------------------------------------
// bf16 flash attention: P kept in registers (MMA1 C-frag == MMA2 A-frag),
// 3-stage cp.async K/V ring, one syncthreads per chunk, mask LDS only for
// the two encoder chunks.
// smem: QS 0..16K | KS 16K..40K (3x8K) | VS 40K..64K (3x8K) | MADD 64K..68.5K
// ---------------------------------------------------------------------------
#define QS_OFF   0
#define KS_OFF   16384
#define VS_OFF   40960
#define MADD_OFF 65536
#define ATT_SMEM 70144

__device__ __forceinline__ void prefetch_kv(uint32_t sbase,
    const __nv_bfloat16* Kg, const __nv_bfloat16* Vg, int c, int slot, int tid)
{
#pragma unroll
    for (int j = 0; j < 4; j++) {
        int i = tid + (j << 8);
        int sel = i >> 9, ch = (i >> 3) & 63, seg = i & 7;
        const __nv_bfloat16* src = (sel ? Vg : Kg) + ch * LP_ + (c << 6) + (seg << 3);
        uint32_t dst = sbase + (sel ? VS_OFF : KS_OFF) + slot * 8192
                     + (ch << 7) + ((seg ^ (ch & 7)) << 4);
        cp16(dst, src);
    }
}

__global__ __launch_bounds__(256, 2) void attn_bf16_kernel(const unsigned int* __restrict__ mask)
{
    extern __shared__ char smc[];
    const uint32_t sbase = smem_u32(smc);
    int tid = threadIdx.x, lane = tid & 31, wid = tid >> 5;
    int gr = lane >> 2, gc = lane & 3, l7 = lane & 7, g = lane >> 3;
    int bh = blockIdx.y, h = bh & 7;
    int t0 = blockIdx.x << 7;
    int r0w = wid << 4;

    const __nv_bfloat16* Qg = g_qp + (size_t)bh * 64 * T_;
    const __nv_bfloat16* Kg = g_kp + (size_t)bh * 64 * LP_;
    const __nv_bfloat16* Vg = g_vp + (size_t)bh * 64 * LP_;

    // mask add only needed for cols >= 1024
    float* madd = (float*)(smc + MADD_OFF);
    for (int s = tid; s < 128; s += 256) {
        int col = 1024 + s;
        madd[s] = (col < L_) ? (mask[h * S_ + s] ? 0.f : -10000.f) : -1e30f;
    }

    for (int i = tid; i < 1024; i += 256) {
        int ch = i >> 4, seg = i & 15;
        uint4 v = *(const uint4*)(Qg + ch * T_ + t0 + seg * 8);
        *(uint4*)(smc + QS_OFF + ch * 256 + ((seg ^ (ch & 7)) << 4)) = v;
    }
    __syncthreads();

    uint32_t qf[4][4];
#pragma unroll
    for (int kt = 0; kt < 4; kt++) {
        int ch = kt * 16 + l7 + ((g >> 1) << 3);
        int tb = (r0w << 1) + ((g & 1) << 4);
        ldsm4t(qf[kt], sbase + QS_OFF + ch * 256 + (tb ^ ((ch & 7) << 4)));
    }

    float o[8][4];
#pragma unroll
    for (int nt = 0; nt < 8; nt++)
#pragma unroll
        for (int l = 0; l < 4; l++) o[nt][l] = 0.f;
    float lsum0 = 0.f, lsum1 = 0.f;

    prefetch_kv(sbase, Kg, Vg, 0, 0, tid); CP_COMMIT();
    prefetch_kv(sbase, Kg, Vg, 1, 1, tid); CP_COMMIT();

    int sl0 = 0, sl2 = 2;
    for (int c = 0; c < 18; c++) {
        CP_WAIT1();
        __syncthreads();
        if (c + 2 < 18) prefetch_kv(sbase, Kg, Vg, c + 2, sl2, tid);
        CP_COMMIT();
        uint32_t kb = sbase + KS_OFF + sl0 * 8192;
        uint32_t vb = sbase + VS_OFF + sl0 * 8192;

        // MMA1: S[16-band, 64s] = Q . K^T
        float s8[8][4];
#pragma unroll
        for (int nt = 0; nt < 8; nt++)
#pragma unroll
            for (int l = 0; l < 4; l++) s8[nt][l] = 0.f;
#pragma unroll
        for (int kt = 0; kt < 4; kt++) {
            int ch = kt * 16 + l7 + ((g & 1) << 3);
#pragma unroll
            for (int ntp = 0; ntp < 4; ntp++) {
                uint32_t bf4[4];
                int seg = ntp * 2 + (g >> 1);
                ldsm4t(bf4, kb + (ch << 7) + ((seg ^ (ch & 7)) << 4));
                mma_bf16(s8[ntp * 2],     qf[kt], bf4);
                mma_bf16(s8[ntp * 2 + 1], qf[kt], bf4 + 2);
            }
        }

        // softmax in registers; self chunks have zero additive mask
        if (c < 16) {
#pragma unroll
            for (int nt = 0; nt < 8; nt++) {
                float p0 = __expf(s8[nt][0]), p1 = __expf(s8[nt][1]);
                float p2 = __expf(s8[nt][2]), p3 = __expf(s8[nt][3]);
                lsum0 += p0 + p1; lsum1 += p2 + p3;
                s8[nt][0] = p0; s8[nt][1] = p1; s8[nt][2] = p2; s8[nt][3] = p3;
            }
        } else {
            int colb = ((c - 16) << 6);
#pragma unroll
            for (int nt = 0; nt < 8; nt++) {
                int col = colb + nt * 8 + gc * 2;
                float m0 = madd[col], m1 = madd[col + 1];
                float p0 = __expf(s8[nt][0] + m0), p1 = __expf(s8[nt][1] + m1);
                float p2 = __expf(s8[nt][2] + m0), p3 = __expf(s8[nt][3] + m1);
                lsum0 += p0 + p1; lsum1 += p2 + p3;
                s8[nt][0] = p0; s8[nt][1] = p1; s8[nt][2] = p2; s8[nt][3] = p3;
            }
        }

        // MMA2: O += P . V^T, A-fragments packed straight from registers
#pragma unroll
        for (int kt = 0; kt < 4; kt++) {
            uint32_t af[4];
            af[0] = pku(s8[2 * kt][0],     s8[2 * kt][1]);
            af[1] = pku(s8[2 * kt][2],     s8[2 * kt][3]);
            af[2] = pku(s8[2 * kt + 1][0], s8[2 * kt + 1][1]);
            af[3] = pku(s8[2 * kt + 1][2], s8[2 * kt + 1][3]);
#pragma unroll
            for (int ntp = 0; ntp < 4; ntp++) {
                uint32_t bv4[4];
                int ch = (ntp * 2 + (g >> 1)) * 8 + l7;
                int sseg = kt * 2 + (g & 1);
                ldsm4(bv4, vb + (ch << 7) + ((sseg ^ (ch & 7)) << 4));
                mma_bf16(o[ntp * 2],     af, bv4);
                mma_bf16(o[ntp * 2 + 1], af, bv4 + 2);
            }
        }
        sl0 = (sl0 == 2) ? 0 : sl0 + 1;
        sl2 = (sl2 == 2) ? 0 : sl2 + 1;
    }

    lsum0 += __shfl_xor_sync(0xffffffffu, lsum0, 1);
    lsum0 += __shfl_xor_sync(0xffffffffu, lsum0, 2);
    lsum1 += __shfl_xor_sync(0xffffffffu, lsum1, 1);
    lsum1 += __shfl_xor_sync(0xffffffffu, lsum1, 2);
    float inv0 = 1.f / lsum0, inv1 = 1.f / lsum1;

    __syncthreads();   // all warps done with K/V smem before reuse as tr
    float* tr = (float*)smc;   // [64][132] floats
    int r0g = r0w + gr;
#pragma unroll
    for (int nt = 0; nt < 8; nt++) {
        int ch = nt * 8 + gc * 2;
        tr[ch * 132 + r0g]           = o[nt][0] * inv0;
        tr[(ch + 1) * 132 + r0g]     = o[nt][1] * inv0;
        tr[ch * 132 + r0g + 8]       = o[nt][2] * inv1;
        tr[(ch + 1) * 132 + r0g + 8] = o[nt][3] * inv1;
    }
    __syncthreads();
    __nv_bfloat16* ob = g_attb + ((size_t)(bh >> 3) * C_ + h * CH_) * T_ + t0;
    for (int i = tid; i < 8192; i += 256) {
        int ch = i >> 7, t = i & 127;
        ob[(size_t)ch * T_ + t] = __float2bfloat16_rn(tr[ch * 132 + t]);
    }
}

// ---------------------------------------------------------------------------
extern "C" void kernel_launch(void* const* d_in, const int* in_sizes, int n_in,
                              void* d_out, int out_size)
{
    (void)in_sizes; (void)n_in; (void)out_size;
    const float* x       = (const float*)d_in[0];
    const float* enc     = (const float*)d_in[1];
    const unsigned int* mask = (const unsigned int*)d_in[2];
    const float* gamma   = (const float*)d_in[3];
    const float* beta    = (const float*)d_in[4];
    const float* qkv_w   = (const float*)d_in[5];
    const float* qkv_b   = (const float*)d_in[6];
    const float* ekv_w   = (const float*)d_in[7];
    const float* ekv_b   = (const float*)d_in[8];
    const float* proj_w  = (const float*)d_in[9];
    const float* proj_b  = (const float*)d_in[10];
    float* out = (float*)d_out;

    __nv_bfloat16 *qkvwb, *ekvwb, *projwb, *encb, *nrmb, *attb;
    cudaGetSymbolAddress((void**)&qkvwb, g_qkvwb);
    cudaGetSymbolAddress((void**)&ekvwb, g_ekvwb);
    cudaGetSymbolAddress((void**)&projwb, g_projwb);
    cudaGetSymbolAddress((void**)&encb, g_encb);
    cudaGetSymbolAddress((void**)&nrmb, g_nrmb);
    cudaGetSymbolAddress((void**)&attb, g_attb);

    conv_kernel<<<(NQW + NEW + NPW + NEN) / 256, 256>>>(qkv_w, ekv_w, proj_w, enc);
    gn_kernel<<<B_ * GROUPS_, 256>>>(x, gamma, beta);

    gemm_bf<<<dim3(8, 12, B_), 256>>>(qkvwb, nrmb, qkv_b, nullptr, nullptr,
        1536, 1024, 512, T_, (long long)C_ * T_, 0, 0, 1);
    gemm_bf<<<dim3(1, 8, B_), 256>>>(ekvwb, encb, ekv_b, nullptr, nullptr,
        1024, S_, 512, 128, (long long)C_ * 128, 0, 0, 2);

    cudaFuncSetAttribute(attn_bf16_kernel, cudaFuncAttributeMaxDynamicSharedMemorySize, ATT_SMEM);
    attn_bf16_kernel<<<dim3(8, 64), 256, ATT_SMEM>>>(mask);

    gemm_bf<<<dim3(8, 4, B_), 256>>>(projwb, attb, proj_b, x, out,
        512, 1024, 512, T_, (long long)C_ * T_, T_, (long long)C_ * T_, 0);
}

// round 9
// speedup vs baseline: 8.7397x; 1.0276x over previous
#include <cuda_runtime.h>
#include <cuda_bf16.h>
#include <cstdint>

#define B_      8
#define C_      512
#define T_      1024
#define HEADS_  8
#define CH_     64
#define S_      77
#define L_      1101
#define LP_     1152
#define GROUPS_ 32
#define CPG_    16

// Scratch (static device globals)
static __device__ __nv_bfloat16 g_nrmb[B_ * C_ * T_];
static __device__ __nv_bfloat16 g_attb[B_ * C_ * T_];
static __device__ __nv_bfloat16 g_qp[B_ * HEADS_ * CH_ * T_];   // [bh][ch][t], pre-scaled 1/8
static __device__ __nv_bfloat16 g_kp[B_ * HEADS_ * CH_ * LP_];  // [bh][ch][self|enc|pad]
static __device__ __nv_bfloat16 g_vp[B_ * HEADS_ * CH_ * LP_];
static __device__ __nv_bfloat16 g_qkvwb[1536 * 512];
static __device__ __nv_bfloat16 g_ekvwb[1024 * 512];
static __device__ __nv_bfloat16 g_projwb[512 * 512];
static __device__ __nv_bfloat16 g_encb[B_ * 512 * 128];

// ---------------------------------------------------------------------------
// PTX helpers
// ---------------------------------------------------------------------------
__device__ __forceinline__ uint32_t smem_u32(const void* p) {
    uint32_t a;
    asm("{ .reg .u64 t; cvta.to.shared.u64 t, %1; cvt.u32.u64 %0, t; }" : "=r"(a) : "l"(p));
    return a;
}
__device__ __forceinline__ void mma_bf16(float* c, const uint32_t* a, const uint32_t* b) {
    asm volatile("mma.sync.aligned.m16n8k16.row.col.f32.bf16.bf16.f32 "
        "{%0,%1,%2,%3}, {%4,%5,%6,%7}, {%8,%9}, {%0,%1,%2,%3};"
        : "+f"(c[0]), "+f"(c[1]), "+f"(c[2]), "+f"(c[3])
        : "r"(a[0]), "r"(a[1]), "r"(a[2]), "r"(a[3]), "r"(b[0]), "r"(b[1]));
}
__device__ __forceinline__ void ldsm4(uint32_t* r, uint32_t a) {
    asm volatile("ldmatrix.sync.aligned.m8n8.x4.shared.b16 {%0,%1,%2,%3}, [%4];"
        : "=r"(r[0]), "=r"(r[1]), "=r"(r[2]), "=r"(r[3]) : "r"(a));
}
__device__ __forceinline__ void ldsm4t(uint32_t* r, uint32_t a) {
    asm volatile("ldmatrix.sync.aligned.m8n8.x4.trans.shared.b16 {%0,%1,%2,%3}, [%4];"
        : "=r"(r[0]), "=r"(r[1]), "=r"(r[2]), "=r"(r[3]) : "r"(a));
}
__device__ __forceinline__ void cp16(uint32_t dst, const void* src) {
    asm volatile("cp.async.cg.shared.global [%0], [%1], 16;" :: "r"(dst), "l"(src));
}
#define CP_COMMIT() asm volatile("cp.async.commit_group;" ::: "memory")
#define CP_WAIT2()  asm volatile("cp.async.wait_group 2;" ::: "memory")

__device__ __forceinline__ __nv_bfloat162 pack2(float a, float b) {
    __nv_bfloat162 w;
    w.x = __float2bfloat16_rn(a);
    w.y = __float2bfloat16_rn(b);
    return w;
}
__device__ __forceinline__ uint32_t pku(float lo, float hi) {
    __nv_bfloat162 t = pack2(lo, hi);
    return *reinterpret_cast<uint32_t*>(&t);
}

// ---------------------------------------------------------------------------
// Fused prep: weight/encoder bf16 conversion + GroupNorm32
// ---------------------------------------------------------------------------
#define NQW 786432
#define NEW 524288
#define NPW 262144
#define NEN 524288
#define NCONVB 8192    // conv blocks; GN blocks follow

__global__ __launch_bounds__(256) void prep_kernel(
    const float* __restrict__ x, const float* __restrict__ gamma,
    const float* __restrict__ beta,
    const float* __restrict__ qkvw, const float* __restrict__ ekvw,
    const float* __restrict__ projw, const float* __restrict__ enc)
{
    if (blockIdx.x < NCONVB) {
        int i = blockIdx.x * 256 + threadIdx.x;
        if (i < NQW) g_qkvwb[i] = __float2bfloat16_rn(qkvw[i]);
        else if (i < NQW + NEW) g_ekvwb[i - NQW] = __float2bfloat16_rn(ekvw[i - NQW]);
        else if (i < NQW + NEW + NPW) g_projwb[i - NQW - NEW] = __float2bfloat16_rn(projw[i - NQW - NEW]);
        else {
            int e = i - NQW - NEW - NPW;
            int t = e & 127, row = e >> 7;
            g_encb[e] = (t < S_) ? __float2bfloat16_rn(enc[row * S_ + t]) : __nv_bfloat16(0.f);
        }
        return;
    }
    int bg = blockIdx.x - NCONVB;
    int b = bg / GROUPS_, g = bg % GROUPS_;
    const float* xp = x + ((size_t)b * C_ + g * CPG_) * T_;
    __nv_bfloat16* op = g_nrmb + ((size_t)b * C_ + g * CPG_) * T_;
    const int N = CPG_ * T_;

    float s = 0.f, q = 0.f;
    for (int i = threadIdx.x; i < N; i += 256) {
        float v = xp[i];
        s += v; q = fmaf(v, v, q);
    }
    __shared__ float rs[256], rq[256];
    rs[threadIdx.x] = s; rq[threadIdx.x] = q;
    __syncthreads();
    for (int o = 128; o > 0; o >>= 1) {
        if (threadIdx.x < o) { rs[threadIdx.x] += rs[threadIdx.x + o]; rq[threadIdx.x] += rq[threadIdx.x + o]; }
        __syncthreads();
    }
    float mean = rs[0] * (1.f / N);
    float var  = rq[0] * (1.f / N) - mean * mean;
    float inv  = rsqrtf(var + 1e-5f);
    for (int i = threadIdx.x; i < N; i += 256) {
        int c = g * CPG_ + (i >> 10);
        op[i] = __float2bfloat16_rn((xp[i] - mean) * inv * gamma[c] + beta[c]);
    }
}

// ---------------------------------------------------------------------------
// Epilogue pack writer (head-major row decode)
// ---------------------------------------------------------------------------
__device__ __forceinline__ void write_pack(int mode, int z, int m, int n, float v0, float v1, int N) {
    int h, type, ch;
    if (mode == 1) {
        h = m / 192;
        int sub = m - h * 192;
        type = sub >> 6; ch = sub & 63;
    } else {
        h = m >> 7;
        type = (m >> 6) & 1; ch = m & 63;
    }
    size_t row = (size_t)(z * 8 + h) * 64 + ch;
    if (mode == 1) {
        if (type == 0) {
            *(__nv_bfloat162*)&g_qp[row * T_ + n] = pack2(v0 * 0.125f, v1 * 0.125f);
        } else {
            __nv_bfloat16* p = (type == 1 ? g_kp : g_vp) + row * LP_ + n;
            *(__nv_bfloat162*)p = pack2(v0, v1);
        }
    } else {
        __nv_bfloat16* p = (type == 0 ? g_kp : g_vp) + row * LP_ + 1024 + n;
        if (n + 1 < N)      *(__nv_bfloat162*)p = pack2(v0, v1);
        else if (n < N)     *p = __float2bfloat16_rn(v0);
    }
}

// ---------------------------------------------------------------------------
// bf16 mma.sync GEMM, 4-stage cp.async pipeline (prefetch distance 3).
// Dynamic smem 64KB: A slots [0..32K), B slots [32K..64K), 8KB each.
// Optional fused second problem occupying the last gridDim.y row (ekv).
// ---------------------------------------------------------------------------
#define GEMM_SMEM 65536

__global__ __launch_bounds__(256, 2) void gemm_bf(
    const __nv_bfloat16* __restrict__ A, const __nv_bfloat16* __restrict__ Bm,
    const float* __restrict__ bias, const float* __restrict__ res,
    float* __restrict__ Cm, int N, int K, int ldb, long long sB,
    int ldc, long long sC, int mode,
    const __nv_bfloat16* __restrict__ A2, const __nv_bfloat16* __restrict__ B2,
    const float* __restrict__ bias2, int N2, int ldb2, long long sB2, int mode2)
{
    extern __shared__ __nv_bfloat16 dsm[];
    const uint32_t sa = smem_u32(dsm), sb = sa + 32768;

    int bm, bn;
    if (A2 && blockIdx.y == gridDim.y - 1) {
        A = A2; Bm = B2; bias = bias2; N = N2; ldb = ldb2; sB = sB2; mode = mode2;
        bm = blockIdx.x << 7; bn = 0;
    } else {
        bm = blockIdx.y << 7; bn = blockIdx.x << 7;
    }

    int tid = threadIdx.x, wid = tid >> 5, lane = tid & 31;
    int wm = (wid >> 2) << 6, wn = (wid & 3) << 5;
    int gr = lane >> 2, gc = lane & 3;

    const __nv_bfloat16* Ab = A + (size_t)bm * K;
    const __nv_bfloat16* Bb = Bm + (size_t)blockIdx.z * sB + bn;

    int a_m  = (lane & 7) + (((lane >> 3) & 1) << 3);
    int a_kc = lane >> 4;
    int b_kr = (lane & 7) + (((lane >> 3) & 1) << 3);
    int b_sg = (wid & 3) * 4 + (lane >> 4);

    float c[4][4][4];
#pragma unroll
    for (int i = 0; i < 4; i++)
#pragma unroll
        for (int j = 0; j < 4; j++)
#pragma unroll
            for (int l = 0; l < 4; l++) c[i][j][l] = 0.f;

    auto load_tiles = [&](int k0, int slot) {
#pragma unroll
        for (int j = 0; j < 2; j++) {
            int idx = tid + (j << 8);
            int m = idx >> 2, kc = idx & 3;
            cp16(sa + slot * 8192 + m * 64 + ((kc ^ ((m >> 1) & 3)) << 4),
                 Ab + (size_t)m * K + k0 + kc * 8);
        }
#pragma unroll
        for (int j = 0; j < 2; j++) {
            int idx = tid + (j << 8);
            int k = idx >> 4, seg = idx & 15;
            cp16(sb + slot * 8192 + k * 256 + ((seg ^ (k & 7)) << 4),
                 Bb + (size_t)(k0 + k) * ldb + seg * 8);
        }
    };

    int nsteps = K >> 5;
    load_tiles(0, 0); CP_COMMIT();
    load_tiles(32, 1); CP_COMMIT();
    load_tiles(64, 2); CP_COMMIT();

    for (int s = 0; s < nsteps; s++) {
        CP_WAIT2();
        __syncthreads();
        if (s + 3 < nsteps) load_tiles((s + 3) << 5, (s + 3) & 3);
        CP_COMMIT();
        uint32_t ab = sa + (s & 3) * 8192, bb = sb + (s & 3) * 8192;

#pragma unroll
        for (int kt = 0; kt < 2; kt++) {
            uint32_t af[4][4];
            int kc = (kt << 1) + a_kc;
#pragma unroll
            for (int mt = 0; mt < 4; mt++) {
                int m = wm + (mt << 4) + a_m;
                ldsm4(af[mt], ab + m * 64 + ((kc ^ ((m >> 1) & 3)) << 4));
            }
            uint32_t bf[4][2];
            int kr = (kt << 4) + b_kr;
#pragma unroll
            for (int np = 0; np < 2; np++) {
                uint32_t t4[4];
                int seg = b_sg + (np << 1);
                ldsm4t(t4, bb + kr * 256 + ((seg ^ (kr & 7)) << 4));
                bf[np * 2][0] = t4[0]; bf[np * 2][1] = t4[1];
                bf[np * 2 + 1][0] = t4[2]; bf[np * 2 + 1][1] = t4[3];
            }
#pragma unroll
            for (int mt = 0; mt < 4; mt++)
#pragma unroll
                for (int nf = 0; nf < 4; nf++)
                    mma_bf16(c[mt][nf], af[mt], bf[nf]);
        }
    }

    float* Cp = Cm ? (Cm + (size_t)blockIdx.z * sC) : nullptr;
    const float* Rp = res ? (res + (size_t)blockIdx.z * sC) : nullptr;

#pragma unroll
    for (int mt = 0; mt < 4; mt++) {
        int m0 = bm + wm + (mt << 4) + gr;
        float bv0 = bias[m0], bv1 = bias[m0 + 8];
#pragma unroll
        for (int nt = 0; nt < 4; nt++) {
            int n = bn + wn + (nt << 3) + (gc << 1);
            float v0 = c[mt][nt][0] + bv0, v1 = c[mt][nt][1] + bv0;
            float v2 = c[mt][nt][2] + bv1, v3 = c[mt][nt][3] + bv1;
            if (mode == 0) {
                float a0 = v0, a1 = v1, a2 = v2, a3 = v3;
                if (Rp) {
                    a0 += Rp[(size_t)m0 * ldc + n];       a1 += Rp[(size_t)m0 * ldc + n + 1];
                    a2 += Rp[(size_t)(m0 + 8) * ldc + n]; a3 += Rp[(size_t)(m0 + 8) * ldc + n + 1];
                }
                Cp[(size_t)m0 * ldc + n] = a0;       Cp[(size_t)m0 * ldc + n + 1] = a1;
                Cp[(size_t)(m0 + 8) * ldc + n] = a2; Cp[(size_t)(m0 + 8) * ldc + n + 1] = a3;
            } else {
                write_pack(mode, blockIdx.z, m0, n, v0, v1, N);
                write_pack(mode, blockIdx.z, m0 + 8, n, v2, v3, N);
            }
        }
    }
}

// ---------------------------------------------------------------------------
// bf16 flash attention: P in registers, 4-slot cp.async K/V ring (distance 3),
// one syncthreads per chunk, mask LDS only for the two encoder chunks.
// smem: QS 0..16K | KS 16K..48K (4x8K) | VS 48K..80K (4x8K) | MADD 80K..
// ---------------------------------------------------------------------------
#define QS_OFF   0
#define KS_OFF   16384
#define VS_OFF   49152
#define MADD_OFF 81920
#define ATT_SMEM 82944

__device__ __forceinline__ void prefetch_kv(uint32_t sbase,
    const __nv_bfloat16* Kg, const __nv_bfloat16* Vg, int c, int slot, int tid)
{
#pragma unroll
    for (int j = 0; j < 4; j++) {
        int i = tid + (j << 8);
        int sel = i >> 9, ch = (i >> 3) & 63, seg = i & 7;
        const __nv_bfloat16* src = (sel ? Vg : Kg) + ch * LP_ + (c << 6) + (seg << 3);
        uint32_t dst = sbase + (sel ? VS_OFF : KS_OFF) + slot * 8192
                     + (ch << 7) + ((seg ^ (ch & 7)) << 4);
        cp16(dst, src);
    }
}

__global__ __launch_bounds__(256, 2) void attn_bf16_kernel(const unsigned int* __restrict__ mask)
{
    extern __shared__ char smc[];
    const uint32_t sbase = smem_u32(smc);
    int tid = threadIdx.x, lane = tid & 31, wid = tid >> 5;
    int gr = lane >> 2, gc = lane & 3, l7 = lane & 7, g = lane >> 3;
    int bh = blockIdx.y, h = bh & 7;
    int t0 = blockIdx.x << 7;
    int r0w = wid << 4;

    const __nv_bfloat16* Qg = g_qp + (size_t)bh * 64 * T_;
    const __nv_bfloat16* Kg = g_kp + (size_t)bh * 64 * LP_;
    const __nv_bfloat16* Vg = g_vp + (size_t)bh * 64 * LP_;

    float* madd = (float*)(smc + MADD_OFF);
    for (int s = tid; s < 128; s += 256) {
        int col = 1024 + s;
        madd[s] = (col < L_) ? (mask[h * S_ + s] ? 0.f : -10000.f) : -1e30f;
    }

    for (int i = tid; i < 1024; i += 256) {
        int ch = i >> 4, seg = i & 15;
        uint4 v = *(const uint4*)(Qg + ch * T_ + t0 + seg * 8);
        *(uint4*)(smc + QS_OFF + ch * 256 + ((seg ^ (ch & 7)) << 4)) = v;
    }
    __syncthreads();

    uint32_t qf[4][4];
#pragma unroll
    for (int kt = 0; kt < 4; kt++) {
        int ch = kt * 16 + l7 + ((g >> 1) << 3);
        int tb = (r0w << 1) + ((g & 1) << 4);
        ldsm4t(qf[kt], sbase + QS_OFF + ch * 256 + (tb ^ ((ch & 7) << 4)));
    }

    float o[8][4];
#pragma unroll
    for (int nt = 0; nt < 8; nt++)
#pragma unroll
        for (int l = 0; l < 4; l++) o[nt][l] = 0.f;
    float lsum0 = 0.f, lsum1 = 0.f;

    prefetch_kv(sbase, Kg, Vg, 0, 0, tid); CP_COMMIT();
    prefetch_kv(sbase, Kg, Vg, 1, 1, tid); CP_COMMIT();
    prefetch_kv(sbase, Kg, Vg, 2, 2, tid); CP_COMMIT();

    for (int c = 0; c < 18; c++) {
        CP_WAIT2();
        __syncthreads();
        if (c + 3 < 18) prefetch_kv(sbase, Kg, Vg, c + 3, (c + 3) & 3, tid);
        CP_COMMIT();
        uint32_t kb = sbase + KS_OFF + (c & 3) * 8192;
        uint32_t vb = sbase + VS_OFF + (c & 3) * 8192;

        // MMA1: S[16-band, 64s] = Q . K^T
        float s8[8][4];
#pragma unroll
        for (int nt = 0; nt < 8; nt++)
#pragma unroll
            for (int l = 0; l < 4; l++) s8[nt][l] = 0.f;
#pragma unroll
        for (int kt = 0; kt < 4; kt++) {
            int ch = kt * 16 + l7 + ((g & 1) << 3);
#pragma unroll
            for (int ntp = 0; ntp < 4; ntp++) {
                uint32_t bf4[4];
                int seg = ntp * 2 + (g >> 1);
                ldsm4t(bf4, kb + (ch << 7) + ((seg ^ (ch & 7)) << 4));
                mma_bf16(s8[ntp * 2],     qf[kt], bf4);
                mma_bf16(s8[ntp * 2 + 1], qf[kt], bf4 + 2);
            }
        }

        // softmax in registers; self chunks have zero additive mask
        if (c < 16) {
#pragma unroll
            for (int nt = 0; nt < 8; nt++) {
                float p0 = __expf(s8[nt][0]), p1 = __expf(s8[nt][1]);
                float p2 = __expf(s8[nt][2]), p3 = __expf(s8[nt][3]);
                lsum0 += p0 + p1; lsum1 += p2 + p3;
                s8[nt][0] = p0; s8[nt][1] = p1; s8[nt][2] = p2; s8[nt][3] = p3;
            }
        } else {
            int colb = ((c - 16) << 6);
#pragma unroll
            for (int nt = 0; nt < 8; nt++) {
                int col = colb + nt * 8 + gc * 2;
                float m0 = madd[col], m1 = madd[col + 1];
                float p0 = __expf(s8[nt][0] + m0), p1 = __expf(s8[nt][1] + m1);
                float p2 = __expf(s8[nt][2] + m0), p3 = __expf(s8[nt][3] + m1);
                lsum0 += p0 + p1; lsum1 += p2 + p3;
                s8[nt][0] = p0; s8[nt][1] = p1; s8[nt][2] = p2; s8[nt][3] = p3;
            }
        }

        // MMA2: O += P . V^T, A-fragments packed straight from registers
#pragma unroll
        for (int kt = 0; kt < 4; kt++) {
            uint32_t af[4];
            af[0] = pku(s8[2 * kt][0],     s8[2 * kt][1]);
            af[1] = pku(s8[2 * kt][2],     s8[2 * kt][3]);
            af[2] = pku(s8[2 * kt + 1][0], s8[2 * kt + 1][1]);
            af[3] = pku(s8[2 * kt + 1][2], s8[2 * kt + 1][3]);
#pragma unroll
            for (int ntp = 0; ntp < 4; ntp++) {
                uint32_t bv4[4];
                int ch = (ntp * 2 + (g >> 1)) * 8 + l7;
                int sseg = kt * 2 + (g & 1);
                ldsm4(bv4, vb + (ch << 7) + ((sseg ^ (ch & 7)) << 4));
                mma_bf16(o[ntp * 2],     af, bv4);
                mma_bf16(o[ntp * 2 + 1], af, bv4 + 2);
            }
        }
    }

    lsum0 += __shfl_xor_sync(0xffffffffu, lsum0, 1);
    lsum0 += __shfl_xor_sync(0xffffffffu, lsum0, 2);
    lsum1 += __shfl_xor_sync(0xffffffffu, lsum1, 1);
    lsum1 += __shfl_xor_sync(0xffffffffu, lsum1, 2);
    float inv0 = 1.f / lsum0, inv1 = 1.f / lsum1;

    __syncthreads();
    float* tr = (float*)smc;   // [64][132] floats
    int r0g = r0w + gr;
#pragma unroll
    for (int nt = 0; nt < 8; nt++) {
        int ch = nt * 8 + gc * 2;
        tr[ch * 132 + r0g]           = o[nt][0] * inv0;
        tr[(ch + 1) * 132 + r0g]     = o[nt][1] * inv0;
        tr[ch * 132 + r0g + 8]       = o[nt][2] * inv1;
        tr[(ch + 1) * 132 + r0g + 8] = o[nt][3] * inv1;
    }
    __syncthreads();
    __nv_bfloat16* ob = g_attb + ((size_t)(bh >> 3) * C_ + h * CH_) * T_ + t0;
    for (int i = tid; i < 8192; i += 256) {
        int ch = i >> 7, t = i & 127;
        ob[(size_t)ch * T_ + t] = __float2bfloat16_rn(tr[ch * 132 + t]);
    }
}

// ---------------------------------------------------------------------------
extern "C" void kernel_launch(void* const* d_in, const int* in_sizes, int n_in,
                              void* d_out, int out_size)
{
    (void)in_sizes; (void)n_in; (void)out_size;
    const float* x       = (const float*)d_in[0];
    const float* enc     = (const float*)d_in[1];
    const unsigned int* mask = (const unsigned int*)d_in[2];
    const float* gamma   = (const float*)d_in[3];
    const float* beta    = (const float*)d_in[4];
    const float* qkv_w   = (const float*)d_in[5];
    const float* qkv_b   = (const float*)d_in[6];
    const float* ekv_w   = (const float*)d_in[7];
    const float* ekv_b   = (const float*)d_in[8];
    const float* proj_w  = (const float*)d_in[9];
    const float* proj_b  = (const float*)d_in[10];
    float* out = (float*)d_out;

    __nv_bfloat16 *qkvwb, *ekvwb, *projwb, *encb, *nrmb, *attb;
    cudaGetSymbolAddress((void**)&qkvwb, g_qkvwb);
    cudaGetSymbolAddress((void**)&ekvwb, g_ekvwb);
    cudaGetSymbolAddress((void**)&projwb, g_projwb);
    cudaGetSymbolAddress((void**)&encb, g_encb);
    cudaGetSymbolAddress((void**)&nrmb, g_nrmb);
    cudaGetSymbolAddress((void**)&attb, g_attb);

    cudaFuncSetAttribute(gemm_bf, cudaFuncAttributeMaxDynamicSharedMemorySize, GEMM_SMEM);
    cudaFuncSetAttribute(attn_bf16_kernel, cudaFuncAttributeMaxDynamicSharedMemorySize, ATT_SMEM);

    // 1. fused weight/encoder conversion + GroupNorm
    prep_kernel<<<NCONVB + B_ * GROUPS_, 256>>>(x, gamma, beta, qkv_w, ekv_w, proj_w, enc);

    // 2. fused qkv + ekv projections (last grid.y row = ekv)
    gemm_bf<<<dim3(8, 13, B_), 256, GEMM_SMEM>>>(qkvwb, nrmb, qkv_b, nullptr, nullptr,
        1024, 512, T_, (long long)C_ * T_, 0, 0, 1,
        ekvwb, encb, ekv_b, S_, 128, (long long)512 * 128, 2);

    // 3. bf16 flash attention
    attn_bf16_kernel<<<dim3(8, 64), 256, ATT_SMEM>>>(mask);

    // 4. output projection + bias + residual -> d_out
    gemm_bf<<<dim3(8, 4, B_), 256, GEMM_SMEM>>>(projwb, attb, proj_b, x, out,
        1024, 512, T_, (long long)C_ * T_, T_, (long long)C_ * T_, 0,
        nullptr, nullptr, nullptr, 0, 0, 0, 0);
}

// round 10
// speedup vs baseline: 9.0719x; 1.0380x over previous
#include <cuda_runtime.h>
#include <cuda_bf16.h>
#include <cstdint>

#define B_      8
#define C_      512
#define T_      1024
#define HEADS_  8
#define CH_     64
#define S_      77
#define L_      1101
#define LP_     1152
#define GROUPS_ 32
#define CPG_    16

// Scratch (static device globals)
static __device__ __nv_bfloat16 g_nrmb[B_ * C_ * T_];
static __device__ __nv_bfloat16 g_attb[B_ * C_ * T_];
static __device__ __nv_bfloat16 g_qp[B_ * HEADS_ * CH_ * T_];   // [bh][ch][t], pre-scaled 1/8
static __device__ __nv_bfloat16 g_kp[B_ * HEADS_ * CH_ * LP_];  // [bh][ch][self|enc|pad]
static __device__ __nv_bfloat16 g_vp[B_ * HEADS_ * CH_ * LP_];
static __device__ __nv_bfloat16 g_qkvwb[1536 * 512];
static __device__ __nv_bfloat16 g_ekvwb[1024 * 512];
static __device__ __nv_bfloat16 g_projwb[512 * 512];
static __device__ __nv_bfloat16 g_encb[B_ * 512 * 128];

// ---------------------------------------------------------------------------
// PTX helpers
// ---------------------------------------------------------------------------
__device__ __forceinline__ uint32_t smem_u32(const void* p) {
    uint32_t a;
    asm("{ .reg .u64 t; cvta.to.shared.u64 t, %1; cvt.u32.u64 %0, t; }" : "=r"(a) : "l"(p));
    return a;
}
__device__ __forceinline__ void mma_bf16(float* c, const uint32_t* a, const uint32_t* b) {
    asm volatile("mma.sync.aligned.m16n8k16.row.col.f32.bf16.bf16.f32 "
        "{%0,%1,%2,%3}, {%4,%5,%6,%7}, {%8,%9}, {%0,%1,%2,%3};"
        : "+f"(c[0]), "+f"(c[1]), "+f"(c[2]), "+f"(c[3])
        : "r"(a[0]), "r"(a[1]), "r"(a[2]), "r"(a[3]), "r"(b[0]), "r"(b[1]));
}
__device__ __forceinline__ void ldsm4(uint32_t* r, uint32_t a) {
    asm volatile("ldmatrix.sync.aligned.m8n8.x4.shared.b16 {%0,%1,%2,%3}, [%4];"
        : "=r"(r[0]), "=r"(r[1]), "=r"(r[2]), "=r"(r[3]) : "r"(a));
}
__device__ __forceinline__ void ldsm4t(uint32_t* r, uint32_t a) {
    asm volatile("ldmatrix.sync.aligned.m8n8.x4.trans.shared.b16 {%0,%1,%2,%3}, [%4];"
        : "=r"(r[0]), "=r"(r[1]), "=r"(r[2]), "=r"(r[3]) : "r"(a));
}
__device__ __forceinline__ void cp16(uint32_t dst, const void* src) {
    asm volatile("cp.async.cg.shared.global [%0], [%1], 16;" :: "r"(dst), "l"(src));
}
#define CP_COMMIT() asm volatile("cp.async.commit_group;" ::: "memory")
#define CP_WAIT1()  asm volatile("cp.async.wait_group 1;" ::: "memory")
#define CP_WAIT2()  asm volatile("cp.async.wait_group 2;" ::: "memory")

__device__ __forceinline__ __nv_bfloat162 pack2(float a, float b) {
    __nv_bfloat162 w;
    w.x = __float2bfloat16_rn(a);
    w.y = __float2bfloat16_rn(b);
    return w;
}
__device__ __forceinline__ uint32_t pku(float lo, float hi) {
    __nv_bfloat162 t = pack2(lo, hi);
    return *reinterpret_cast<uint32_t*>(&t);
}

// ---------------------------------------------------------------------------
// Fused prep: weight/encoder bf16 conversion + GroupNorm32
// ---------------------------------------------------------------------------
#define NQW 786432
#define NEW 524288
#define NPW 262144
#define NEN 524288
#define NCONVB 8192

__global__ __launch_bounds__(256) void prep_kernel(
    const float* __restrict__ x, const float* __restrict__ gamma,
    const float* __restrict__ beta,
    const float* __restrict__ qkvw, const float* __restrict__ ekvw,
    const float* __restrict__ projw, const float* __restrict__ enc)
{
    if (blockIdx.x < NCONVB) {
        int i = blockIdx.x * 256 + threadIdx.x;
        if (i < NQW) g_qkvwb[i] = __float2bfloat16_rn(qkvw[i]);
        else if (i < NQW + NEW) g_ekvwb[i - NQW] = __float2bfloat16_rn(ekvw[i - NQW]);
        else if (i < NQW + NEW + NPW) g_projwb[i - NQW - NEW] = __float2bfloat16_rn(projw[i - NQW - NEW]);
        else {
            int e = i - NQW - NEW - NPW;
            int t = e & 127, row = e >> 7;
            g_encb[e] = (t < S_) ? __float2bfloat16_rn(enc[row * S_ + t]) : __nv_bfloat16(0.f);
        }
        return;
    }
    int bg = blockIdx.x - NCONVB;
    int b = bg / GROUPS_, g = bg % GROUPS_;
    const float* xp = x + ((size_t)b * C_ + g * CPG_) * T_;
    __nv_bfloat16* op = g_nrmb + ((size_t)b * C_ + g * CPG_) * T_;
    const int N = CPG_ * T_;

    float s = 0.f, q = 0.f;
    for (int i = threadIdx.x; i < N; i += 256) {
        float v = xp[i];
        s += v; q = fmaf(v, v, q);
    }
    __shared__ float rs[256], rq[256];
    rs[threadIdx.x] = s; rq[threadIdx.x] = q;
    __syncthreads();
    for (int o = 128; o > 0; o >>= 1) {
        if (threadIdx.x < o) { rs[threadIdx.x] += rs[threadIdx.x + o]; rq[threadIdx.x] += rq[threadIdx.x + o]; }
        __syncthreads();
    }
    float mean = rs[0] * (1.f / N);
    float var  = rq[0] * (1.f / N) - mean * mean;
    float inv  = rsqrtf(var + 1e-5f);
    for (int i = threadIdx.x; i < N; i += 256) {
        int c = g * CPG_ + (i >> 10);
        op[i] = __float2bfloat16_rn((xp[i] - mean) * inv * gamma[c] + beta[c]);
    }
}

// ---------------------------------------------------------------------------
// Epilogue pack writer (head-major row decode)
// ---------------------------------------------------------------------------
__device__ __forceinline__ void write_pack(int mode, int z, int m, int n, float v0, float v1, int N) {
    int h, type, ch;
    if (mode == 1) {
        h = m / 192;
        int sub = m - h * 192;
        type = sub >> 6; ch = sub & 63;
    } else {
        h = m >> 7;
        type = (m >> 6) & 1; ch = m & 63;
    }
    size_t row = (size_t)(z * 8 + h) * 64 + ch;
    if (mode == 1) {
        if (type == 0) {
            *(__nv_bfloat162*)&g_qp[row * T_ + n] = pack2(v0 * 0.125f, v1 * 0.125f);
        } else {
            __nv_bfloat16* p = (type == 1 ? g_kp : g_vp) + row * LP_ + n;
            *(__nv_bfloat162*)p = pack2(v0, v1);
        }
    } else {
        __nv_bfloat16* p = (type == 0 ? g_kp : g_vp) + row * LP_ + 1024 + n;
        if (n + 1 < N)      *(__nv_bfloat162*)p = pack2(v0, v1);
        else if (n < N)     *p = __float2bfloat16_rn(v0);
    }
}

// ---------------------------------------------------------------------------
// bf16 mma.sync GEMM, K-step 64, 3-slot cp.async ring (32KB slots).
// smem 96KB: A slots [0..48K) (16KB each, 128B rows, seg^(m&7) swizzle),
//            B slots [48K..96K) (16KB each, 256B rows, seg^(k&7) swizzle).
// Optional fused second problem occupying the last gridDim.y row (ekv).
// ---------------------------------------------------------------------------
#define GEMM_SMEM 98304

__global__ __launch_bounds__(256, 2) void gemm_bf(
    const __nv_bfloat16* __restrict__ A, const __nv_bfloat16* __restrict__ Bm,
    const float* __restrict__ bias, const float* __restrict__ res,
    float* __restrict__ Cm, int N, int K, int ldb, long long sB,
    int ldc, long long sC, int mode,
    const __nv_bfloat16* __restrict__ A2, const __nv_bfloat16* __restrict__ B2,
    const float* __restrict__ bias2, int N2, int ldb2, long long sB2, int mode2)
{
    extern __shared__ __nv_bfloat16 dsm[];
    const uint32_t sa = smem_u32(dsm), sb = sa + 49152;

    int bm, bn;
    if (A2 && blockIdx.y == gridDim.y - 1) {
        A = A2; Bm = B2; bias = bias2; N = N2; ldb = ldb2; sB = sB2; mode = mode2;
        bm = blockIdx.x << 7; bn = 0;
    } else {
        bm = blockIdx.y << 7; bn = blockIdx.x << 7;
    }

    int tid = threadIdx.x, wid = tid >> 5, lane = tid & 31;
    int wm = (wid >> 2) << 6, wn = (wid & 3) << 5;
    int gr = lane >> 2, gc = lane & 3;

    const __nv_bfloat16* Ab = A + (size_t)bm * K;
    const __nv_bfloat16* Bb = Bm + (size_t)blockIdx.z * sB + bn;

    int a_m  = (lane & 7) + (((lane >> 3) & 1) << 3);
    int a_kc = lane >> 4;
    int b_kr = (lane & 7) + (((lane >> 3) & 1) << 3);
    int b_sg = (wid & 3) * 4 + (lane >> 4);

    float c[4][4][4];
#pragma unroll
    for (int i = 0; i < 4; i++)
#pragma unroll
        for (int j = 0; j < 4; j++)
#pragma unroll
            for (int l = 0; l < 4; l++) c[i][j][l] = 0.f;

    // one K-step = 64 k: A 128x64 (16KB), B 64x128 (16KB); 8 cp16/thread
    auto load_tiles = [&](int k0, int slot) {
#pragma unroll
        for (int j = 0; j < 4; j++) {
            int idx = tid + (j << 8);
            int m = idx >> 3, s8 = idx & 7;
            cp16(sa + slot * 16384 + m * 128 + ((s8 ^ (m & 7)) << 4),
                 Ab + (size_t)m * K + k0 + s8 * 8);
        }
#pragma unroll
        for (int j = 0; j < 4; j++) {
            int idx = tid + (j << 8);
            int k = idx >> 4, seg = idx & 15;
            cp16(sb + slot * 16384 + k * 256 + ((seg ^ (k & 7)) << 4),
                 Bb + (size_t)(k0 + k) * ldb + seg * 8);
        }
    };

    int nsteps = K >> 6;   // K=512 -> 8
    load_tiles(0, 0); CP_COMMIT();
    load_tiles(64, 1); CP_COMMIT();

    int sl0 = 0, sl2 = 2;
    for (int s = 0; s < nsteps; s++) {
        CP_WAIT1();
        __syncthreads();
        if (s + 2 < nsteps) load_tiles((s + 2) << 6, sl2);
        CP_COMMIT();
        uint32_t ab = sa + sl0 * 16384, bb = sb + sl0 * 16384;

#pragma unroll
        for (int kt = 0; kt < 4; kt++) {
            uint32_t af[4][4];
            int s8 = (kt << 1) + a_kc;
#pragma unroll
            for (int mt = 0; mt < 4; mt++) {
                int m = wm + (mt << 4) + a_m;
                ldsm4(af[mt], ab + m * 128 + ((s8 ^ (m & 7)) << 4));
            }
            uint32_t bf[4][2];
            int kr = (kt << 4) + b_kr;
#pragma unroll
            for (int np = 0; np < 2; np++) {
                uint32_t t4[4];
                int seg = b_sg + (np << 1);
                ldsm4t(t4, bb + kr * 256 + ((seg ^ (kr & 7)) << 4));
                bf[np * 2][0] = t4[0]; bf[np * 2][1] = t4[1];
                bf[np * 2 + 1][0] = t4[2]; bf[np * 2 + 1][1] = t4[3];
            }
#pragma unroll
            for (int mt = 0; mt < 4; mt++)
#pragma unroll
                for (int nf = 0; nf < 4; nf++)
                    mma_bf16(c[mt][nf], af[mt], bf[nf]);
        }
        sl0 = (sl0 == 2) ? 0 : sl0 + 1;
        sl2 = (sl2 == 2) ? 0 : sl2 + 1;
    }

    float* Cp = Cm ? (Cm + (size_t)blockIdx.z * sC) : nullptr;
    const float* Rp = res ? (res + (size_t)blockIdx.z * sC) : nullptr;

#pragma unroll
    for (int mt = 0; mt < 4; mt++) {
        int m0 = bm + wm + (mt << 4) + gr;
        float bv0 = bias[m0], bv1 = bias[m0 + 8];
#pragma unroll
        for (int nt = 0; nt < 4; nt++) {
            int n = bn + wn + (nt << 3) + (gc << 1);
            float v0 = c[mt][nt][0] + bv0, v1 = c[mt][nt][1] + bv0;
            float v2 = c[mt][nt][2] + bv1, v3 = c[mt][nt][3] + bv1;
            if (mode == 0) {
                if (Rp) {
                    float2 r0 = *(const float2*)&Rp[(size_t)m0 * ldc + n];
                    float2 r1 = *(const float2*)&Rp[(size_t)(m0 + 8) * ldc + n];
                    v0 += r0.x; v1 += r0.y; v2 += r1.x; v3 += r1.y;
                }
                *(float2*)&Cp[(size_t)m0 * ldc + n]       = make_float2(v0, v1);
                *(float2*)&Cp[(size_t)(m0 + 8) * ldc + n] = make_float2(v2, v3);
            } else {
                write_pack(mode, blockIdx.z, m0, n, v0, v1, N);
                write_pack(mode, blockIdx.z, m0 + 8, n, v2, v3, N);
            }
        }
    }
}

// ---------------------------------------------------------------------------
// bf16 flash attention: P in registers, 6-slot cp.async K/V ring consumed in
// chunk PAIRS (one syncthreads per 2 chunks), mask LDS only for encoder cols.
// smem: QS 0..16K | KS 16K..64K (6x8K) | VS 64K..112K (6x8K) | MADD 112K..
// ---------------------------------------------------------------------------
#define QS_OFF   0
#define KS_OFF   16384
#define VS_OFF   65536
#define MADD_OFF 114688
#define ATT_SMEM 115200

__device__ __forceinline__ void prefetch_kv(uint32_t sbase,
    const __nv_bfloat16* Kg, const __nv_bfloat16* Vg, int c, int slot, int tid)
{
#pragma unroll
    for (int j = 0; j < 4; j++) {
        int i = tid + (j << 8);
        int sel = i >> 9, ch = (i >> 3) & 63, seg = i & 7;
        const __nv_bfloat16* src = (sel ? Vg : Kg) + ch * LP_ + (c << 6) + (seg << 3);
        uint32_t dst = sbase + (sel ? VS_OFF : KS_OFF) + slot * 8192
                     + (ch << 7) + ((seg ^ (ch & 7)) << 4);
        cp16(dst, src);
    }
}

__global__ __launch_bounds__(256, 2) void attn_bf16_kernel(const unsigned int* __restrict__ mask)
{
    extern __shared__ char smc[];
    const uint32_t sbase = smem_u32(smc);
    int tid = threadIdx.x, lane = tid & 31, wid = tid >> 5;
    int gr = lane >> 2, gc = lane & 3, l7 = lane & 7, g = lane >> 3;
    int bh = blockIdx.y, h = bh & 7;
    int t0 = blockIdx.x << 7;
    int r0w = wid << 4;

    const __nv_bfloat16* Qg = g_qp + (size_t)bh * 64 * T_;
    const __nv_bfloat16* Kg = g_kp + (size_t)bh * 64 * LP_;
    const __nv_bfloat16* Vg = g_vp + (size_t)bh * 64 * LP_;

    float* madd = (float*)(smc + MADD_OFF);
    for (int s = tid; s < 128; s += 256) {
        int col = 1024 + s;
        madd[s] = (col < L_) ? (mask[h * S_ + s] ? 0.f : -10000.f) : -1e30f;
    }

    for (int i = tid; i < 1024; i += 256) {
        int ch = i >> 4, seg = i & 15;
        uint4 v = *(const uint4*)(Qg + ch * T_ + t0 + seg * 8);
        *(uint4*)(smc + QS_OFF + ch * 256 + ((seg ^ (ch & 7)) << 4)) = v;
    }
    __syncthreads();

    uint32_t qf[4][4];
#pragma unroll
    for (int kt = 0; kt < 4; kt++) {
        int ch = kt * 16 + l7 + ((g >> 1) << 3);
        int tb = (r0w << 1) + ((g & 1) << 4);
        ldsm4t(qf[kt], sbase + QS_OFF + ch * 256 + (tb ^ ((ch & 7) << 4)));
    }

    float o[8][4];
#pragma unroll
    for (int nt = 0; nt < 8; nt++)
#pragma unroll
        for (int l = 0; l < 4; l++) o[nt][l] = 0.f;
    float lsum0 = 0.f, lsum1 = 0.f;

    // one 64-key chunk: MMA1 -> softmax (regs) -> MMA2
    auto process = [&](int c, uint32_t kb, uint32_t vb) {
        float s8[8][4];
#pragma unroll
        for (int nt = 0; nt < 8; nt++)
#pragma unroll
            for (int l = 0; l < 4; l++) s8[nt][l] = 0.f;
#pragma unroll
        for (int kt = 0; kt < 4; kt++) {
            int ch = kt * 16 + l7 + ((g & 1) << 3);
#pragma unroll
            for (int ntp = 0; ntp < 4; ntp++) {
                uint32_t bf4[4];
                int seg = ntp * 2 + (g >> 1);
                ldsm4t(bf4, kb + (ch << 7) + ((seg ^ (ch & 7)) << 4));
                mma_bf16(s8[ntp * 2],     qf[kt], bf4);
                mma_bf16(s8[ntp * 2 + 1], qf[kt], bf4 + 2);
            }
        }
        if (c < 16) {
#pragma unroll
            for (int nt = 0; nt < 8; nt++) {
                float p0 = __expf(s8[nt][0]), p1 = __expf(s8[nt][1]);
                float p2 = __expf(s8[nt][2]), p3 = __expf(s8[nt][3]);
                lsum0 += p0 + p1; lsum1 += p2 + p3;
                s8[nt][0] = p0; s8[nt][1] = p1; s8[nt][2] = p2; s8[nt][3] = p3;
            }
        } else {
            int colb = ((c - 16) << 6);
#pragma unroll
            for (int nt = 0; nt < 8; nt++) {
                int col = colb + nt * 8 + gc * 2;
                float m0 = madd[col], m1 = madd[col + 1];
                float p0 = __expf(s8[nt][0] + m0), p1 = __expf(s8[nt][1] + m1);
                float p2 = __expf(s8[nt][2] + m0), p3 = __expf(s8[nt][3] + m1);
                lsum0 += p0 + p1; lsum1 += p2 + p3;
                s8[nt][0] = p0; s8[nt][1] = p1; s8[nt][2] = p2; s8[nt][3] = p3;
            }
        }
#pragma unroll
        for (int kt = 0; kt < 4; kt++) {
            uint32_t af[4];
            af[0] = pku(s8[2 * kt][0],     s8[2 * kt][1]);
            af[1] = pku(s8[2 * kt][2],     s8[2 * kt][3]);
            af[2] = pku(s8[2 * kt + 1][0], s8[2 * kt + 1][1]);
            af[3] = pku(s8[2 * kt + 1][2], s8[2 * kt + 1][3]);
#pragma unroll
            for (int ntp = 0; ntp < 4; ntp++) {
                uint32_t bv4[4];
                int ch = (ntp * 2 + (g >> 1)) * 8 + l7;
                int sseg = kt * 2 + (g & 1);
                ldsm4(bv4, vb + (ch << 7) + ((sseg ^ (ch & 7)) << 4));
                mma_bf16(o[ntp * 2],     af, bv4);
                mma_bf16(o[ntp * 2 + 1], af, bv4 + 2);
            }
        }
    };

    prefetch_kv(sbase, Kg, Vg, 0, 0, tid); CP_COMMIT();
    prefetch_kv(sbase, Kg, Vg, 1, 1, tid); CP_COMMIT();
    prefetch_kv(sbase, Kg, Vg, 2, 2, tid); CP_COMMIT();
    prefetch_kv(sbase, Kg, Vg, 3, 3, tid); CP_COMMIT();

    for (int it = 0; it < 9; it++) {
        int c0 = it << 1;
        CP_WAIT2();           // all but newest 2 groups -> chunks <= c0+1 ready
        __syncthreads();
        if (c0 + 4 < 18) prefetch_kv(sbase, Kg, Vg, c0 + 4, (c0 + 4) % 6, tid);
        CP_COMMIT();          // always commit (empty groups keep the count)
        if (c0 + 5 < 18) prefetch_kv(sbase, Kg, Vg, c0 + 5, (c0 + 5) % 6, tid);
        CP_COMMIT();
        int s0 = c0 % 6, s1 = (c0 + 1) % 6;
        process(c0,     sbase + KS_OFF + s0 * 8192, sbase + VS_OFF + s0 * 8192);
        process(c0 + 1, sbase + KS_OFF + s1 * 8192, sbase + VS_OFF + s1 * 8192);
    }

    lsum0 += __shfl_xor_sync(0xffffffffu, lsum0, 1);
    lsum0 += __shfl_xor_sync(0xffffffffu, lsum0, 2);
    lsum1 += __shfl_xor_sync(0xffffffffu, lsum1, 1);
    lsum1 += __shfl_xor_sync(0xffffffffu, lsum1, 2);
    float inv0 = 1.f / lsum0, inv1 = 1.f / lsum1;

    __syncthreads();
    float* tr = (float*)smc;   // [64][132] floats
    int r0g = r0w + gr;
#pragma unroll
    for (int nt = 0; nt < 8; nt++) {
        int ch = nt * 8 + gc * 2;
        tr[ch * 132 + r0g]           = o[nt][0] * inv0;
        tr[(ch + 1) * 132 + r0g]     = o[nt][1] * inv0;
        tr[ch * 132 + r0g + 8]       = o[nt][2] * inv1;
        tr[(ch + 1) * 132 + r0g + 8] = o[nt][3] * inv1;
    }
    __syncthreads();
    __nv_bfloat16* ob = g_attb + ((size_t)(bh >> 3) * C_ + h * CH_) * T_ + t0;
    for (int i = tid; i < 8192; i += 256) {
        int ch = i >> 7, t = i & 127;
        ob[(size_t)ch * T_ + t] = __float2bfloat16_rn(tr[ch * 132 + t]);
    }
}

// ---------------------------------------------------------------------------
extern "C" void kernel_launch(void* const* d_in, const int* in_sizes, int n_in,
                              void* d_out, int out_size)
{
    (void)in_sizes; (void)n_in; (void)out_size;
    const float* x       = (const float*)d_in[0];
    const float* enc     = (const float*)d_in[1];
    const unsigned int* mask = (const unsigned int*)d_in[2];
    const float* gamma   = (const float*)d_in[3];
    const float* beta    = (const float*)d_in[4];
    const float* qkv_w   = (const float*)d_in[5];
    const float* qkv_b   = (const float*)d_in[6];
    const float* ekv_w   = (const float*)d_in[7];
    const float* ekv_b   = (const float*)d_in[8];
    const float* proj_w  = (const float*)d_in[9];
    const float* proj_b  = (const float*)d_in[10];
    float* out = (float*)d_out;

    __nv_bfloat16 *qkvwb, *ekvwb, *projwb, *encb, *nrmb, *attb;
    cudaGetSymbolAddress((void**)&qkvwb, g_qkvwb);
    cudaGetSymbolAddress((void**)&ekvwb, g_ekvwb);
    cudaGetSymbolAddress((void**)&projwb, g_projwb);
    cudaGetSymbolAddress((void**)&encb, g_encb);
    cudaGetSymbolAddress((void**)&nrmb, g_nrmb);
    cudaGetSymbolAddress((void**)&attb, g_attb);

    cudaFuncSetAttribute(gemm_bf, cudaFuncAttributeMaxDynamicSharedMemorySize, GEMM_SMEM);
    cudaFuncSetAttribute(attn_bf16_kernel, cudaFuncAttributeMaxDynamicSharedMemorySize, ATT_SMEM);

    // 1. fused weight/encoder conversion + GroupNorm
    prep_kernel<<<NCONVB + B_ * GROUPS_, 256>>>(x, gamma, beta, qkv_w, ekv_w, proj_w, enc);

    // 2. fused qkv + ekv projections (last grid.y row = ekv)
    gemm_bf<<<dim3(8, 13, B_), 256, GEMM_SMEM>>>(qkvwb, nrmb, qkv_b, nullptr, nullptr,
        1024, 512, T_, (long long)C_ * T_, 0, 0, 1,
        ekvwb, encb, ekv_b, S_, 128, (long long)512 * 128, 2);

    // 3. bf16 flash attention
    attn_bf16_kernel<<<dim3(8, 64), 256, ATT_SMEM>>>(mask);

    // 4. output projection + bias + residual -> d_out
    gemm_bf<<<dim3(8, 4, B_), 256, GEMM_SMEM>>>(projwb, attb, proj_b, x, out,
        1024, 512, T_, (long long)C_ * T_, T_, (long long)C_ * T_, 0,
        nullptr, nullptr, nullptr, 0, 0, 0, 0);
}